// round 11
// baseline (speedup 1.0000x reference)
#include <cuda_runtime.h>
#include <cuda_fp16.h>
#include <mma.h>
#include <cstdint>

using namespace nvcuda;

// Problem constants: N=50000, E=640000, D=H=128, OUT=32
#define MAXN 50000
#define MAXE 640000

// Scratch (device globals — no allocation allowed)
__device__ float g_W3[128 * 384];     // [Wp+Wp@WuA | Wp@WmA | Wp@WmB]
__device__ float g_b3[384];           // [bp+bp@WuA | bp@WmA | bp@WmB+bm]
__device__ float g_Y[MAXN * 128];     // hc = h0 + c   fp32
__device__ half2 g_a[MAXN * 64];      // a = h0@WmA (+bias part)   fp16
__device__ half2 g_b[MAXN * 64];      // b = h0@WmB + bm           fp16
__device__ half2 g_pool[MAXN * 64];   // pooled mean               fp16
__device__ float g_gsum[128];         // graph-level sum of normalized hn
__device__ int   g_deg[MAXN];         // per-dst degree
__device__ int   g_off[MAXN];         // CSR offsets
__device__ int   g_cur[MAXN];         // scatter cursors
__device__ int   g_elist[MAXE];       // src ids grouped by dst

// ---------------------------------------------------------------------------
// Combined weight build + deg zeroing.
// W3 col-blocks: 0: Wp + Wp@WuA, 1: Wp@WmA, 2: Wp@WmB
// b3           : 0: bp + bp@WuA, 1: bp@WmA, 2: bp@WmB + bm
// ---------------------------------------------------------------------------
__global__ void k_prep(const float* __restrict__ Wp, const float* __restrict__ bp,
                       const float* __restrict__ Wm, const float* __restrict__ bm,
                       const float* __restrict__ Wu, int n) {
    int idx = blockIdx.x * blockDim.x + threadIdx.x;
    if (idx < n) g_deg[idx] = 0;
    if (idx < 3 * 16384) {
        int blk = idx >> 14;
        int rem = idx & 16383;
        int i = rem >> 7, jj = rem & 127;
        const float* M = (blk == 0) ? Wu : ((blk == 1) ? Wm : Wm + 16384);
        float s = (blk == 0) ? Wp[i * 128 + jj] : 0.f;
        for (int k = 0; k < 128; k++) s += Wp[i * 128 + k] * M[k * 128 + jj];
        g_W3[i * 384 + blk * 128 + jj] = s;
    }
    if (idx < 384) {
        int blk = idx >> 7, jj = idx & 127;
        const float* M = (blk == 0) ? Wu : ((blk == 1) ? Wm : Wm + 16384);
        float s = (blk == 0) ? bp[jj] : ((blk == 2) ? bm[jj] : 0.f);
        for (int k = 0; k < 128; k++) s += bp[k] * M[k * 128 + jj];
        g_b3[idx] = s;
    }
}

// ---------------------------------------------------------------------------
// fp16 wmma GEMM, CTA = 128x128 tile, K=128 in smem.
// mode 0 (grid.x=3): Y = x @ W3 + b3; blk 0->g_Y hc (fp32), 1->g_a, 2->g_b (fp16)
// mode 1 (grid.x=1): fused upd-GEMM (pool fp16 @ WuB) + relu + LN + graph-pool
// ---------------------------------------------------------------------------
#define LDH 136
#define LDC 132
#define SM_A_BYTES (128 * LDH * 2)          // 34816
#define SACC_OFF   (2 * SM_A_BYTES)         // 69632 (Cs ends at 67584)
#define GSM_SZ     (SACC_OFF + 4096)        // 73728

__global__ void __launch_bounds__(256, 2) k_gemm_h(const float* __restrict__ Xext,
                                                   const float* __restrict__ Wext,
                                                   const float* __restrict__ biasExt,
                                                   const float* __restrict__ gamma,
                                                   const float* __restrict__ beta,
                                                   int n, int mode) {
    extern __shared__ __align__(16) char smw[];
    half*  As = (half*)smw;
    half*  Bs = (half*)(smw + SM_A_BYTES);
    float* Cs = (float*)smw;                    // overlaps A+B (after sync)
    float* sacc = (float*)(smw + SACC_OFF);     // [8][128] LN partials

    const float* W    = mode ? Wext   : g_W3;
    const float* bias = mode ? biasExt : g_b3;
    const int wp4     = mode ? 32 : 96;    // W row pitch (float4)
    const int rowBase = blockIdx.y * 128;
    const int cb4     = blockIdx.x * 32;   // W column base (float4)

    const int tid = threadIdx.x;
    const int wid = tid >> 5;
    const int lane = tid & 31;

    // ---- Fill A and B tiles ----
    const float4* X4 = (const float4*)Xext;
    const float4* W4 = (const float4*)W;
    const uint2*  P2 = (const uint2*)g_pool;
    #pragma unroll
    for (int it = 0; it < 16; it++) {
        int i = tid + it * 256;
        int m = i >> 5, c4 = i & 31;
        int row = rowBase + m;
        if (mode == 0) {
            float4 v = make_float4(0.f, 0.f, 0.f, 0.f);
            if (row < n) v = X4[(size_t)row * 32 + c4];
            half2* da = (half2*)&As[m * LDH + c4 * 4];
            da[0] = __floats2half2_rn(v.x, v.y);
            da[1] = __floats2half2_rn(v.z, v.w);
        } else {
            uint2 u = make_uint2(0u, 0u);
            if (row < n) u = __ldg(P2 + (size_t)row * 32 + c4);
            *(uint2*)&As[m * LDH + c4 * 4] = u;      // raw fp16 copy
        }
        float4 w = W4[(size_t)m * wp4 + cb4 + c4];
        half2* db = (half2*)&Bs[m * LDH + c4 * 4];
        db[0] = __floats2half2_rn(w.x, w.y);
        db[1] = __floats2half2_rn(w.z, w.w);
    }
    __syncthreads();

    // ---- MMA main loop ----
    const int wrow = (wid & 3) * 32;
    const int wcol = (wid >> 2) * 64;

    wmma::fragment<wmma::accumulator, 16, 16, 16, float> acc[2][4];
    #pragma unroll
    for (int r = 0; r < 2; r++)
        #pragma unroll
        for (int c = 0; c < 4; c++) wmma::fill_fragment(acc[r][c], 0.0f);

    #pragma unroll
    for (int kk = 0; kk < 8; kk++) {
        wmma::fragment<wmma::matrix_a, 16, 16, 16, half, wmma::row_major> af[2];
        wmma::fragment<wmma::matrix_b, 16, 16, 16, half, wmma::row_major> bf[4];
        #pragma unroll
        for (int r = 0; r < 2; r++)
            wmma::load_matrix_sync(af[r], &As[(wrow + r * 16) * LDH + kk * 16], LDH);
        #pragma unroll
        for (int c = 0; c < 4; c++)
            wmma::load_matrix_sync(bf[c], &Bs[(kk * 16) * LDH + wcol + c * 16], LDH);
        #pragma unroll
        for (int r = 0; r < 2; r++)
            #pragma unroll
            for (int c = 0; c < 4; c++)
                wmma::mma_sync(acc[r][c], af[r], bf[c], acc[r][c]);
    }

    // ---- Stage C (fp32) into smem ----
    __syncthreads();
    #pragma unroll
    for (int r = 0; r < 2; r++)
        #pragma unroll
        for (int c = 0; c < 4; c++)
            wmma::store_matrix_sync(&Cs[(wrow + r * 16) * LDC + wcol + c * 16],
                                    acc[r][c], LDC, wmma::mem_row_major);
    __syncthreads();

    const float4* b4 = (const float4*)bias;

    if (mode == 0) {
        const int blk = blockIdx.x;
        #pragma unroll
        for (int it = 0; it < 16; it++) {
            int i = tid + it * 256;
            int m = i >> 5, c4 = i & 31;
            int row = rowBase + m;
            if (row >= n) continue;
            float4 v = *(float4*)&Cs[m * LDC + c4 * 4];
            float4 bv = b4[cb4 + c4];
            v.x += bv.x; v.y += bv.y; v.z += bv.z; v.w += bv.w;
            if (blk == 0) {
                ((float4*)g_Y)[(size_t)row * 32 + c4] = v;            // hc fp32
            } else {
                half2 h0 = __floats2half2_rn(v.x, v.y);
                half2 h1 = __floats2half2_rn(v.z, v.w);
                half2* dstp = (blk == 1) ? g_a : g_b;
                dstp[(size_t)row * 64 + c4 * 2]     = h0;
                dstp[(size_t)row * 64 + c4 * 2 + 1] = h1;
            }
        }
    } else {
        // ---- Fused: upd + relu(hc+upd+bu) + LayerNorm + graph-pool partials ----
        float4 ga = ((const float4*)gamma)[lane];
        float4 be = ((const float4*)beta)[lane];
        float ax = 0.f, ay = 0.f, az = 0.f, aw = 0.f;
        float4 bv = b4[lane];   // bu

        #pragma unroll
        for (int it = 0; it < 16; it++) {
            int m = wid + it * 8;             // one warp <-> one row
            int row = rowBase + m;
            if (row >= n) continue;
            float4 u  = *(float4*)&Cs[m * LDC + lane * 4];
            float4 hc = ((const float4*)g_Y)[(size_t)row * 32 + lane];
            float vx = fmaxf(hc.x + u.x + bv.x, 0.f);
            float vy = fmaxf(hc.y + u.y + bv.y, 0.f);
            float vz = fmaxf(hc.z + u.z + bv.z, 0.f);
            float vw = fmaxf(hc.w + u.w + bv.w, 0.f);

            float s1 = vx + vy + vz + vw;
            float s2 = vx * vx + vy * vy + vz * vz + vw * vw;
            #pragma unroll
            for (int o = 16; o > 0; o >>= 1) {
                s1 += __shfl_xor_sync(0xFFFFFFFFu, s1, o);
                s2 += __shfl_xor_sync(0xFFFFFFFFu, s2, o);
            }
            float mu  = s1 * (1.f / 128.f);
            float var = s2 * (1.f / 128.f) - mu * mu;
            float is  = rsqrtf(var + 1e-6f);
            ax += (vx - mu) * is * ga.x + be.x;
            ay += (vy - mu) * is * ga.y + be.y;
            az += (vz - mu) * is * ga.z + be.z;
            aw += (vw - mu) * is * ga.w + be.w;
        }

        sacc[wid * 128 + lane * 4 + 0] = ax;
        sacc[wid * 128 + lane * 4 + 1] = ay;
        sacc[wid * 128 + lane * 4 + 2] = az;
        sacc[wid * 128 + lane * 4 + 3] = aw;
        __syncthreads();
        if (tid < 128) {
            float s = 0.f;
            #pragma unroll
            for (int ww = 0; ww < 8; ww++) s += sacc[ww * 128 + tid];
            atomicAdd(&g_gsum[tid], s);
        }
    }
}

// ---------------------------------------------------------------------------
// CSR build: histogram -> single-block scan -> scatter
// ---------------------------------------------------------------------------
__global__ void k_hist(const int* __restrict__ dst, int e) {
    int i = blockIdx.x * blockDim.x + threadIdx.x;
    if (i < e) atomicAdd(&g_deg[dst[i]], 1);
}

__global__ void __launch_bounds__(1024) k_scan(int n) {
    __shared__ int wsum[32];
    int tid = threadIdx.x;
    int lane = tid & 31, wd = tid >> 5;
    int chunk = (n + 1023) / 1024;
    int lo = tid * chunk; if (lo > n) lo = n;
    int hi = lo + chunk;  if (hi > n) hi = n;
    int s = 0;
    for (int i = lo; i < hi; i++) s += g_deg[i];
    int v = s;
    #pragma unroll
    for (int o = 1; o < 32; o <<= 1) {
        int t = __shfl_up_sync(0xFFFFFFFFu, v, o);
        if (lane >= o) v += t;
    }
    if (lane == 31) wsum[wd] = v;
    __syncthreads();
    if (wd == 0) {
        int w = wsum[lane];
        #pragma unroll
        for (int o = 1; o < 32; o <<= 1) {
            int t = __shfl_up_sync(0xFFFFFFFFu, w, o);
            if (lane >= o) w += t;
        }
        wsum[lane] = w;
    }
    __syncthreads();
    int base = v - s + (wd > 0 ? wsum[wd - 1] : 0);
    for (int i = lo; i < hi; i++) {
        g_off[i] = base;
        g_cur[i] = base;
        base += g_deg[i];
    }
    if (tid < 128) g_gsum[tid] = 0.f;
}

__global__ void k_scatter(const int* __restrict__ src, const int* __restrict__ dst, int e) {
    int i = blockIdx.x * blockDim.x + threadIdx.x;
    if (i < e) {
        int pos = atomicAdd(&g_cur[dst[i]], 1);
        g_elist[pos] = src[i];
    }
}

// ---------------------------------------------------------------------------
// Gather: warp per node d. pooled[d] = mean over edges of relu(a[src]+b[d]).
// fp16 a rows (256B random, L2-resident); 2-deep software pipeline for MLP.
// ---------------------------------------------------------------------------
__global__ void __launch_bounds__(256) k_gather(int n) {
    int w = (blockIdx.x * blockDim.x + threadIdx.x) >> 5;
    if (w >= n) return;
    int lane = threadIdx.x & 31;
    int off = g_off[w], deg = g_deg[w];

    float2 vb01 = __half22float2(__ldg(g_b + (size_t)w * 64 + lane * 2));
    float2 vb23 = __half22float2(__ldg(g_b + (size_t)w * 64 + lane * 2 + 1));
    float ax = 0.f, ay = 0.f, az = 0.f, aw = 0.f;

    if (deg > 0) {
        int s = g_elist[off];
        half2 pa0 = __ldg(g_a + (size_t)s * 64 + lane * 2);
        half2 pa1 = __ldg(g_a + (size_t)s * 64 + lane * 2 + 1);
        for (int j = 0; j < deg; j++) {
            int s2 = (j + 1 < deg) ? g_elist[off + j + 1] : 0;
            half2 na0 = __ldg(g_a + (size_t)s2 * 64 + lane * 2);
            half2 na1 = __ldg(g_a + (size_t)s2 * 64 + lane * 2 + 1);
            float2 a01 = __half22float2(pa0);
            float2 a23 = __half22float2(pa1);
            ax += fmaxf(a01.x + vb01.x, 0.f);
            ay += fmaxf(a01.y + vb01.y, 0.f);
            az += fmaxf(a23.x + vb23.x, 0.f);
            aw += fmaxf(a23.y + vb23.y, 0.f);
            pa0 = na0; pa1 = na1;
        }
    }
    float rc = 1.0f / (float)max(deg, 1);
    half2 o01 = __floats2half2_rn(ax * rc, ay * rc);
    half2 o23 = __floats2half2_rn(az * rc, aw * rc);
    g_pool[(size_t)w * 64 + lane * 2]     = o01;
    g_pool[(size_t)w * 64 + lane * 2 + 1] = o23;
}

// ---------------------------------------------------------------------------
__global__ void k_final(const float* __restrict__ Wd, const float* __restrict__ bd,
                        float* __restrict__ out, int n) {
    int o = threadIdx.x;
    if (o >= 32) return;
    float s = 0.f;
    #pragma unroll
    for (int c = 0; c < 128; c++) s += g_gsum[c] * Wd[c * 32 + o];
    out[o] = s / (float)n + bd[o];
}

// ---------------------------------------------------------------------------
extern "C" void kernel_launch(void* const* d_in, const int* in_sizes, int n_in,
                              void* d_out, int out_size) {
    const float* x     = (const float*)d_in[0];
    const int*   esrc  = (const int*)d_in[1];
    const int*   edst  = (const int*)d_in[2];
    const float* Wp    = (const float*)d_in[3];
    const float* bp    = (const float*)d_in[4];
    const float* Wm    = (const float*)d_in[5];
    const float* bm    = (const float*)d_in[6];
    const float* Wu    = (const float*)d_in[7];
    const float* bu    = (const float*)d_in[8];
    const float* gamma = (const float*)d_in[9];
    const float* beta  = (const float*)d_in[10];
    const float* Wd    = (const float*)d_in[11];
    const float* bd    = (const float*)d_in[12];
    float* out = (float*)d_out;

    int n = in_sizes[0] / 128;
    int e = in_sizes[1];
    int rb = (n + 127) / 128;

    cudaFuncSetAttribute(k_gemm_h, cudaFuncAttributeMaxDynamicSharedMemorySize, GSM_SZ);

    // combined weights + deg zero
    k_prep<<<(n + 255) / 256, 256>>>(Wp, bp, Wm, bm, Wu, n);
    // hc | a | b from one GEMM pass
    k_gemm_h<<<dim3(3, rb), 256, GSM_SZ>>>(x, nullptr, nullptr, nullptr, nullptr, n, 0);
    // CSR build + gather (segment mean)
    k_hist<<<(e + 255) / 256, 256>>>(edst, e);
    k_scan<<<1, 1024>>>(n);
    k_scatter<<<(e + 255) / 256, 256>>>(esrc, edst, e);
    k_gather<<<(n * 32 + 255) / 256, 256>>>(n);
    // upd-GEMM fused with relu+LN+graph-pool
    k_gemm_h<<<dim3(1, rb), 256, GSM_SZ>>>(nullptr, Wu + 16384, bu, gamma, beta, n, 1);
    k_final<<<1, 32>>>(Wd, bd, out, n);
}

// round 12
// speedup vs baseline: 1.7100x; 1.7100x over previous
#include <cuda_runtime.h>
#include <cuda_fp16.h>
#include <mma.h>
#include <cstdint>

using namespace nvcuda;

// Problem constants: N=50000, E=640000, D=H=128, OUT=32
#define MAXN 50000
#define MAXE 640000

// Scratch (device globals — no allocation allowed)
__device__ float g_W3[128 * 384];     // [Wp+Wp@WuA | Wp@WmA | Wp@WmB]
__device__ float g_b3[384];           // [bp+bp@WuA | bp@WmA | bp@WmB+bm]
__device__ float g_Y[MAXN * 128];     // hc = h0 + c   fp32
__device__ half2 g_a[MAXN * 64];      // a = h0@WmA                fp16
__device__ half2 g_b[MAXN * 64];      // b = h0@WmB + bm           fp16
__device__ half2 g_pool[MAXN * 64];   // pooled mean               fp16
__device__ float g_gsum[128];         // graph-level sum of normalized hn
__device__ int   g_deg[MAXN];         // per-dst degree
__device__ int   g_off[MAXN];         // CSR offsets
__device__ int   g_cur[MAXN];         // scatter cursors
__device__ int   g_elist[MAXE];       // src ids grouped by dst

// ---------------------------------------------------------------------------
// Combined weight build + deg zeroing.
// W3 col-blocks: 0: Wp + Wp@WuA, 1: Wp@WmA, 2: Wp@WmB
// b3           : 0: bp + bp@WuA, 1: bp@WmA, 2: bp@WmB + bm
// ---------------------------------------------------------------------------
__global__ void k_prep(const float* __restrict__ Wp, const float* __restrict__ bp,
                       const float* __restrict__ Wm, const float* __restrict__ bm,
                       const float* __restrict__ Wu, int n) {
    int idx = blockIdx.x * blockDim.x + threadIdx.x;
    if (idx < n) g_deg[idx] = 0;
    if (idx < 3 * 16384) {
        int blk = idx >> 14;
        int rem = idx & 16383;
        int i = rem >> 7, jj = rem & 127;
        const float* M = (blk == 0) ? Wu : ((blk == 1) ? Wm : Wm + 16384);
        float s = (blk == 0) ? Wp[i * 128 + jj] : 0.f;
        for (int k = 0; k < 128; k++) s += Wp[i * 128 + k] * M[k * 128 + jj];
        g_W3[i * 384 + blk * 128 + jj] = s;
    }
    if (idx < 384) {
        int blk = idx >> 7, jj = idx & 127;
        const float* M = (blk == 0) ? Wu : ((blk == 1) ? Wm : Wm + 16384);
        float s = (blk == 0) ? bp[jj] : ((blk == 2) ? bm[jj] : 0.f);
        for (int k = 0; k < 128; k++) s += bp[k] * M[k * 128 + jj];
        g_b3[idx] = s;
    }
}

// ---------------------------------------------------------------------------
// fp16 wmma GEMM, CTA = 128x128 tile, K=128 in smem.
// mode 0 (grid.x=3): Y = x @ W3 + b3; blk 0->g_Y hc (fp32), 1->g_a, 2->g_b (fp16)
// mode 1 (grid.x=1): fused upd-GEMM (pool fp16 @ WuB) + relu + LN + graph-pool
// ---------------------------------------------------------------------------
#define LDH 136
#define LDC 132
#define SM_A_BYTES (128 * LDH * 2)          // 34816
#define SACC_OFF   (2 * SM_A_BYTES)         // 69632 (Cs ends at 67584)
#define GSM_SZ     (SACC_OFF + 4096)        // 73728

__global__ void __launch_bounds__(256, 2) k_gemm_h(const float* __restrict__ Xext,
                                                   const float* __restrict__ Wext,
                                                   const float* __restrict__ biasExt,
                                                   const float* __restrict__ gamma,
                                                   const float* __restrict__ beta,
                                                   int n, int mode) {
    extern __shared__ __align__(16) char smw[];
    half*  As = (half*)smw;
    half*  Bs = (half*)(smw + SM_A_BYTES);
    float* Cs = (float*)smw;                    // overlaps A+B (after sync)
    float* sacc = (float*)(smw + SACC_OFF);     // [8][128] LN partials

    const float* W    = mode ? Wext   : g_W3;
    const float* bias = mode ? biasExt : g_b3;
    const int wp4     = mode ? 32 : 96;    // W row pitch (float4)
    const int rowBase = blockIdx.y * 128;
    const int cb4     = blockIdx.x * 32;   // W column base (float4)

    const int tid = threadIdx.x;
    const int wid = tid >> 5;
    const int lane = tid & 31;

    // ---- Fill A and B tiles ----
    const float4* X4 = (const float4*)Xext;
    const float4* W4 = (const float4*)W;
    const uint2*  P2 = (const uint2*)g_pool;
    #pragma unroll
    for (int it = 0; it < 16; it++) {
        int i = tid + it * 256;
        int m = i >> 5, c4 = i & 31;
        int row = rowBase + m;
        if (mode == 0) {
            float4 v = make_float4(0.f, 0.f, 0.f, 0.f);
            if (row < n) v = X4[(size_t)row * 32 + c4];
            half2* da = (half2*)&As[m * LDH + c4 * 4];
            da[0] = __floats2half2_rn(v.x, v.y);
            da[1] = __floats2half2_rn(v.z, v.w);
        } else {
            uint2 u = make_uint2(0u, 0u);
            if (row < n) u = __ldg(P2 + (size_t)row * 32 + c4);
            *(uint2*)&As[m * LDH + c4 * 4] = u;      // raw fp16 copy
        }
        float4 w = W4[(size_t)m * wp4 + cb4 + c4];
        half2* db = (half2*)&Bs[m * LDH + c4 * 4];
        db[0] = __floats2half2_rn(w.x, w.y);
        db[1] = __floats2half2_rn(w.z, w.w);
    }
    __syncthreads();

    // ---- MMA main loop ----
    const int wrow = (wid & 3) * 32;
    const int wcol = (wid >> 2) * 64;

    wmma::fragment<wmma::accumulator, 16, 16, 16, float> acc[2][4];
    #pragma unroll
    for (int r = 0; r < 2; r++)
        #pragma unroll
        for (int c = 0; c < 4; c++) wmma::fill_fragment(acc[r][c], 0.0f);

    #pragma unroll
    for (int kk = 0; kk < 8; kk++) {
        wmma::fragment<wmma::matrix_a, 16, 16, 16, half, wmma::row_major> af[2];
        wmma::fragment<wmma::matrix_b, 16, 16, 16, half, wmma::row_major> bf[4];
        #pragma unroll
        for (int r = 0; r < 2; r++)
            wmma::load_matrix_sync(af[r], &As[(wrow + r * 16) * LDH + kk * 16], LDH);
        #pragma unroll
        for (int c = 0; c < 4; c++)
            wmma::load_matrix_sync(bf[c], &Bs[(kk * 16) * LDH + wcol + c * 16], LDH);
        #pragma unroll
        for (int r = 0; r < 2; r++)
            #pragma unroll
            for (int c = 0; c < 4; c++)
                wmma::mma_sync(acc[r][c], af[r], bf[c], acc[r][c]);
    }

    // ---- Stage C (fp32) into smem ----
    __syncthreads();
    #pragma unroll
    for (int r = 0; r < 2; r++)
        #pragma unroll
        for (int c = 0; c < 4; c++)
            wmma::store_matrix_sync(&Cs[(wrow + r * 16) * LDC + wcol + c * 16],
                                    acc[r][c], LDC, wmma::mem_row_major);
    __syncthreads();

    const float4* b4 = (const float4*)bias;

    if (mode == 0) {
        const int blk = blockIdx.x;
        #pragma unroll
        for (int it = 0; it < 16; it++) {
            int i = tid + it * 256;
            int m = i >> 5, c4 = i & 31;
            int row = rowBase + m;
            if (row >= n) continue;
            float4 v = *(float4*)&Cs[m * LDC + c4 * 4];
            float4 bv = b4[cb4 + c4];
            v.x += bv.x; v.y += bv.y; v.z += bv.z; v.w += bv.w;
            if (blk == 0) {
                ((float4*)g_Y)[(size_t)row * 32 + c4] = v;            // hc fp32
            } else {
                half2 h0 = __floats2half2_rn(v.x, v.y);
                half2 h1 = __floats2half2_rn(v.z, v.w);
                half2* dstp = (blk == 1) ? g_a : g_b;
                dstp[(size_t)row * 64 + c4 * 2]     = h0;
                dstp[(size_t)row * 64 + c4 * 2 + 1] = h1;
            }
        }
    } else {
        // ---- Fused: upd + relu(hc+upd+bu) + LayerNorm + graph-pool partials ----
        float4 ga = ((const float4*)gamma)[lane];
        float4 be = ((const float4*)beta)[lane];
        float ax = 0.f, ay = 0.f, az = 0.f, aw = 0.f;
        float4 bv = b4[lane];   // bu

        #pragma unroll
        for (int it = 0; it < 16; it++) {
            int m = wid + it * 8;             // one warp <-> one row
            int row = rowBase + m;
            if (row >= n) continue;
            float4 u  = *(float4*)&Cs[m * LDC + lane * 4];
            float4 hc = ((const float4*)g_Y)[(size_t)row * 32 + lane];
            float vx = fmaxf(hc.x + u.x + bv.x, 0.f);
            float vy = fmaxf(hc.y + u.y + bv.y, 0.f);
            float vz = fmaxf(hc.z + u.z + bv.z, 0.f);
            float vw = fmaxf(hc.w + u.w + bv.w, 0.f);

            float s1 = vx + vy + vz + vw;
            float s2 = vx * vx + vy * vy + vz * vz + vw * vw;
            #pragma unroll
            for (int o = 16; o > 0; o >>= 1) {
                s1 += __shfl_xor_sync(0xFFFFFFFFu, s1, o);
                s2 += __shfl_xor_sync(0xFFFFFFFFu, s2, o);
            }
            float mu  = s1 * (1.f / 128.f);
            float var = s2 * (1.f / 128.f) - mu * mu;
            float is  = rsqrtf(var + 1e-6f);
            ax += (vx - mu) * is * ga.x + be.x;
            ay += (vy - mu) * is * ga.y + be.y;
            az += (vz - mu) * is * ga.z + be.z;
            aw += (vw - mu) * is * ga.w + be.w;
        }

        sacc[wid * 128 + lane * 4 + 0] = ax;
        sacc[wid * 128 + lane * 4 + 1] = ay;
        sacc[wid * 128 + lane * 4 + 2] = az;
        sacc[wid * 128 + lane * 4 + 3] = aw;
        __syncthreads();
        if (tid < 128) {
            float s = 0.f;
            #pragma unroll
            for (int ww = 0; ww < 8; ww++) s += sacc[ww * 128 + tid];
            atomicAdd(&g_gsum[tid], s);
        }
    }
}

// ---------------------------------------------------------------------------
// CSR build: histogram -> tiled coalesced block scan -> scatter
// ---------------------------------------------------------------------------
__global__ void k_hist(const int* __restrict__ dst, int e) {
    int i = blockIdx.x * blockDim.x + threadIdx.x;
    if (i < e) atomicAdd(&g_deg[dst[i]], 1);
}

__global__ void __launch_bounds__(1024) k_scan(int n) {
    __shared__ int wsum[32];
    __shared__ int stot;
    int tid = threadIdx.x;
    int lane = tid & 31, wd = tid >> 5;
    int running = 0;
    int ntiles = (n + 1023) >> 10;
    for (int p = 0; p < ntiles; p++) {
        int i = (p << 10) + tid;
        int d = (i < n) ? g_deg[i] : 0;       // coalesced tile load
        int v = d;
        #pragma unroll
        for (int o = 1; o < 32; o <<= 1) {
            int t = __shfl_up_sync(0xFFFFFFFFu, v, o);
            if (lane >= o) v += t;
        }
        if (lane == 31) wsum[wd] = v;
        __syncthreads();
        if (wd == 0) {
            int w = wsum[lane];
            #pragma unroll
            for (int o = 1; o < 32; o <<= 1) {
                int t = __shfl_up_sync(0xFFFFFFFFu, w, o);
                if (lane >= o) w += t;
            }
            wsum[lane] = w;
            if (lane == 31) stot = w;
        }
        __syncthreads();
        int excl = running + v - d + (wd ? wsum[wd - 1] : 0);
        if (i < n) { g_off[i] = excl; g_cur[i] = excl; }   // coalesced stores
        running += stot;
        __syncthreads();   // wsum/stot reused next tile
    }
    if (tid < 128) g_gsum[tid] = 0.f;
}

__global__ void k_scatter(const int* __restrict__ src, const int* __restrict__ dst, int e) {
    int i = blockIdx.x * blockDim.x + threadIdx.x;
    if (i < e) {
        int pos = atomicAdd(&g_cur[dst[i]], 1);
        g_elist[pos] = src[i];
    }
}

// ---------------------------------------------------------------------------
// Gather: warp per node d. pooled[d] = mean over edges of relu(a[src]+b[d]).
// fp16 a rows (256B random, L2-resident); 2-deep software pipeline for MLP.
// ---------------------------------------------------------------------------
__global__ void __launch_bounds__(256) k_gather(int n) {
    int w = (blockIdx.x * blockDim.x + threadIdx.x) >> 5;
    if (w >= n) return;
    int lane = threadIdx.x & 31;
    int off = g_off[w], deg = g_deg[w];

    float2 vb01 = __half22float2(__ldg(g_b + (size_t)w * 64 + lane * 2));
    float2 vb23 = __half22float2(__ldg(g_b + (size_t)w * 64 + lane * 2 + 1));
    float ax = 0.f, ay = 0.f, az = 0.f, aw = 0.f;

    if (deg > 0) {
        int s = g_elist[off];
        half2 pa0 = __ldg(g_a + (size_t)s * 64 + lane * 2);
        half2 pa1 = __ldg(g_a + (size_t)s * 64 + lane * 2 + 1);
        for (int j = 0; j < deg; j++) {
            int s2 = (j + 1 < deg) ? g_elist[off + j + 1] : 0;
            half2 na0 = __ldg(g_a + (size_t)s2 * 64 + lane * 2);
            half2 na1 = __ldg(g_a + (size_t)s2 * 64 + lane * 2 + 1);
            float2 a01 = __half22float2(pa0);
            float2 a23 = __half22float2(pa1);
            ax += fmaxf(a01.x + vb01.x, 0.f);
            ay += fmaxf(a01.y + vb01.y, 0.f);
            az += fmaxf(a23.x + vb23.x, 0.f);
            aw += fmaxf(a23.y + vb23.y, 0.f);
            pa0 = na0; pa1 = na1;
        }
    }
    float rc = 1.0f / (float)max(deg, 1);
    half2 o01 = __floats2half2_rn(ax * rc, ay * rc);
    half2 o23 = __floats2half2_rn(az * rc, aw * rc);
    g_pool[(size_t)w * 64 + lane * 2]     = o01;
    g_pool[(size_t)w * 64 + lane * 2 + 1] = o23;
}

// ---------------------------------------------------------------------------
__global__ void k_final(const float* __restrict__ Wd, const float* __restrict__ bd,
                        float* __restrict__ out, int n) {
    int o = threadIdx.x;
    if (o >= 32) return;
    float s = 0.f;
    #pragma unroll
    for (int c = 0; c < 128; c++) s += g_gsum[c] * Wd[c * 32 + o];
    out[o] = s / (float)n + bd[o];
}

// ---------------------------------------------------------------------------
extern "C" void kernel_launch(void* const* d_in, const int* in_sizes, int n_in,
                              void* d_out, int out_size) {
    const float* x     = (const float*)d_in[0];
    const int*   esrc  = (const int*)d_in[1];
    const int*   edst  = (const int*)d_in[2];
    const float* Wp    = (const float*)d_in[3];
    const float* bp    = (const float*)d_in[4];
    const float* Wm    = (const float*)d_in[5];
    const float* bm    = (const float*)d_in[6];
    const float* Wu    = (const float*)d_in[7];
    const float* bu    = (const float*)d_in[8];
    const float* gamma = (const float*)d_in[9];
    const float* beta  = (const float*)d_in[10];
    const float* Wd    = (const float*)d_in[11];
    const float* bd    = (const float*)d_in[12];
    float* out = (float*)d_out;

    int n = in_sizes[0] / 128;
    int e = in_sizes[1];
    int rb = (n + 127) / 128;

    cudaFuncSetAttribute(k_gemm_h, cudaFuncAttributeMaxDynamicSharedMemorySize, GSM_SZ);

    // combined weights + deg zero
    k_prep<<<(n + 255) / 256, 256>>>(Wp, bp, Wm, bm, Wu, n);
    // hc | a | b from one GEMM pass
    k_gemm_h<<<dim3(3, rb), 256, GSM_SZ>>>(x, nullptr, nullptr, nullptr, nullptr, n, 0);
    // CSR build + gather (segment mean)
    k_hist<<<(e + 255) / 256, 256>>>(edst, e);
    k_scan<<<1, 1024>>>(n);
    k_scatter<<<(e + 255) / 256, 256>>>(esrc, edst, e);
    k_gather<<<(n * 32 + 255) / 256, 256>>>(n);
    // upd-GEMM fused with relu+LN+graph-pool
    k_gemm_h<<<dim3(1, rb), 256, GSM_SZ>>>(nullptr, Wu + 16384, bu, gamma, beta, n, 1);
    k_final<<<1, 32>>>(Wd, bd, out, n);
}

// round 13
// speedup vs baseline: 1.9625x; 1.1477x over previous
#include <cuda_runtime.h>
#include <cuda_fp16.h>
#include <mma.h>
#include <cstdint>

using namespace nvcuda;

// Problem constants: N=50000, E=640000, D=H=128, OUT=32
#define MAXN 50000
#define MAXE 640000
#define SCAN_B 1024
#define MAXBLK 64

// Scratch (device globals — no allocation allowed)
__device__ float g_W3[128 * 384];     // [Wp+Wp@WuA | Wp@WmA | Wp@WmB]
__device__ float g_b3[384];           // [bp+bp@WuA | bp@WmA | bp@WmB+bm]
__device__ float g_Y[MAXN * 128];     // hc = h0 + c   fp32
__device__ half2 g_a[MAXN * 64];      // a = h0@WmA                fp16
__device__ half2 g_b[MAXN * 64];      // b = h0@WmB + bm           fp16
__device__ half2 g_pool[MAXN * 64];   // pooled mean               fp16
__device__ float g_gsum[128];         // graph-level sum of normalized hn
__device__ int   g_deg[MAXN];         // per-dst degree
__device__ int   g_off[MAXN];         // CSR offsets
__device__ int   g_cur[MAXN];         // scatter cursors
__device__ int   g_elist[MAXE];       // src ids grouped by dst
__device__ int   g_bsum[MAXBLK];      // per-block scan totals

// ---------------------------------------------------------------------------
// Combined weight build + deg zeroing.
// W3 col-blocks: 0: Wp + Wp@WuA, 1: Wp@WmA, 2: Wp@WmB
// b3           : 0: bp + bp@WuA, 1: bp@WmA, 2: bp@WmB + bm
// ---------------------------------------------------------------------------
__global__ void k_prep(const float* __restrict__ Wp, const float* __restrict__ bp,
                       const float* __restrict__ Wm, const float* __restrict__ bm,
                       const float* __restrict__ Wu, int n) {
    int idx = blockIdx.x * blockDim.x + threadIdx.x;
    if (idx < n) g_deg[idx] = 0;
    if (idx < 3 * 16384) {
        int blk = idx >> 14;
        int rem = idx & 16383;
        int i = rem >> 7, jj = rem & 127;
        const float* M = (blk == 0) ? Wu : ((blk == 1) ? Wm : Wm + 16384);
        float s = (blk == 0) ? Wp[i * 128 + jj] : 0.f;
        for (int k = 0; k < 128; k++) s += Wp[i * 128 + k] * M[k * 128 + jj];
        g_W3[i * 384 + blk * 128 + jj] = s;
    }
    if (idx < 384) {
        int blk = idx >> 7, jj = idx & 127;
        const float* M = (blk == 0) ? Wu : ((blk == 1) ? Wm : Wm + 16384);
        float s = (blk == 0) ? bp[jj] : ((blk == 2) ? bm[jj] : 0.f);
        for (int k = 0; k < 128; k++) s += bp[k] * M[k * 128 + jj];
        g_b3[idx] = s;
    }
}

// ---------------------------------------------------------------------------
// fp16 wmma GEMM, CTA = 128x128 tile, K=128 in smem.
// mode 0 (grid.x=3): Y = x @ W3 + b3; blk 0->g_Y hc (fp32), 1->g_a, 2->g_b (fp16)
// mode 1 (grid.x=1): fused upd-GEMM (pool fp16 @ WuB) + relu + LN + graph-pool
// ---------------------------------------------------------------------------
#define LDH 136
#define LDC 132
#define SM_A_BYTES (128 * LDH * 2)          // 34816
#define SACC_OFF   (2 * SM_A_BYTES)         // 69632 (Cs ends at 67584)
#define GSM_SZ     (SACC_OFF + 4096)        // 73728

__global__ void __launch_bounds__(256, 2) k_gemm_h(const float* __restrict__ Xext,
                                                   const float* __restrict__ Wext,
                                                   const float* __restrict__ biasExt,
                                                   const float* __restrict__ gamma,
                                                   const float* __restrict__ beta,
                                                   int n, int mode) {
    extern __shared__ __align__(16) char smw[];
    half*  As = (half*)smw;
    half*  Bs = (half*)(smw + SM_A_BYTES);
    float* Cs = (float*)smw;                    // overlaps A+B (after sync)
    float* sacc = (float*)(smw + SACC_OFF);     // [8][128] LN partials

    const float* W    = mode ? Wext   : g_W3;
    const float* bias = mode ? biasExt : g_b3;
    const int wp4     = mode ? 32 : 96;    // W row pitch (float4)
    const int rowBase = blockIdx.y * 128;
    const int cb4     = blockIdx.x * 32;   // W column base (float4)

    const int tid = threadIdx.x;
    const int wid = tid >> 5;
    const int lane = tid & 31;

    // ---- Fill A and B tiles ----
    const float4* X4 = (const float4*)Xext;
    const float4* W4 = (const float4*)W;
    const uint2*  P2 = (const uint2*)g_pool;
    #pragma unroll
    for (int it = 0; it < 16; it++) {
        int i = tid + it * 256;
        int m = i >> 5, c4 = i & 31;
        int row = rowBase + m;
        if (mode == 0) {
            float4 v = make_float4(0.f, 0.f, 0.f, 0.f);
            if (row < n) v = X4[(size_t)row * 32 + c4];
            half2* da = (half2*)&As[m * LDH + c4 * 4];
            da[0] = __floats2half2_rn(v.x, v.y);
            da[1] = __floats2half2_rn(v.z, v.w);
        } else {
            uint2 u = make_uint2(0u, 0u);
            if (row < n) u = __ldg(P2 + (size_t)row * 32 + c4);
            *(uint2*)&As[m * LDH + c4 * 4] = u;      // raw fp16 copy
        }
        float4 w = W4[(size_t)m * wp4 + cb4 + c4];
        half2* db = (half2*)&Bs[m * LDH + c4 * 4];
        db[0] = __floats2half2_rn(w.x, w.y);
        db[1] = __floats2half2_rn(w.z, w.w);
    }
    __syncthreads();

    // ---- MMA main loop ----
    const int wrow = (wid & 3) * 32;
    const int wcol = (wid >> 2) * 64;

    wmma::fragment<wmma::accumulator, 16, 16, 16, float> acc[2][4];
    #pragma unroll
    for (int r = 0; r < 2; r++)
        #pragma unroll
        for (int c = 0; c < 4; c++) wmma::fill_fragment(acc[r][c], 0.0f);

    #pragma unroll
    for (int kk = 0; kk < 8; kk++) {
        wmma::fragment<wmma::matrix_a, 16, 16, 16, half, wmma::row_major> af[2];
        wmma::fragment<wmma::matrix_b, 16, 16, 16, half, wmma::row_major> bf[4];
        #pragma unroll
        for (int r = 0; r < 2; r++)
            wmma::load_matrix_sync(af[r], &As[(wrow + r * 16) * LDH + kk * 16], LDH);
        #pragma unroll
        for (int c = 0; c < 4; c++)
            wmma::load_matrix_sync(bf[c], &Bs[(kk * 16) * LDH + wcol + c * 16], LDH);
        #pragma unroll
        for (int r = 0; r < 2; r++)
            #pragma unroll
            for (int c = 0; c < 4; c++)
                wmma::mma_sync(acc[r][c], af[r], bf[c], acc[r][c]);
    }

    // ---- Stage C (fp32) into smem ----
    __syncthreads();
    #pragma unroll
    for (int r = 0; r < 2; r++)
        #pragma unroll
        for (int c = 0; c < 4; c++)
            wmma::store_matrix_sync(&Cs[(wrow + r * 16) * LDC + wcol + c * 16],
                                    acc[r][c], LDC, wmma::mem_row_major);
    __syncthreads();

    const float4* b4 = (const float4*)bias;

    if (mode == 0) {
        const int blk = blockIdx.x;
        #pragma unroll
        for (int it = 0; it < 16; it++) {
            int i = tid + it * 256;
            int m = i >> 5, c4 = i & 31;
            int row = rowBase + m;
            if (row >= n) continue;
            float4 v = *(float4*)&Cs[m * LDC + c4 * 4];
            float4 bv = b4[cb4 + c4];
            v.x += bv.x; v.y += bv.y; v.z += bv.z; v.w += bv.w;
            if (blk == 0) {
                ((float4*)g_Y)[(size_t)row * 32 + c4] = v;            // hc fp32
            } else {
                half2 h0 = __floats2half2_rn(v.x, v.y);
                half2 h1 = __floats2half2_rn(v.z, v.w);
                half2* dstp = (blk == 1) ? g_a : g_b;
                dstp[(size_t)row * 64 + c4 * 2]     = h0;
                dstp[(size_t)row * 64 + c4 * 2 + 1] = h1;
            }
        }
    } else {
        // ---- Fused: upd + relu(hc+upd+bu) + LayerNorm + graph-pool partials ----
        float4 ga = ((const float4*)gamma)[lane];
        float4 be = ((const float4*)beta)[lane];
        float ax = 0.f, ay = 0.f, az = 0.f, aw = 0.f;
        float4 bv = b4[lane];   // bu

        #pragma unroll
        for (int it = 0; it < 16; it++) {
            int m = wid + it * 8;             // one warp <-> one row
            int row = rowBase + m;
            if (row >= n) continue;
            float4 u  = *(float4*)&Cs[m * LDC + lane * 4];
            float4 hc = ((const float4*)g_Y)[(size_t)row * 32 + lane];
            float vx = fmaxf(hc.x + u.x + bv.x, 0.f);
            float vy = fmaxf(hc.y + u.y + bv.y, 0.f);
            float vz = fmaxf(hc.z + u.z + bv.z, 0.f);
            float vw = fmaxf(hc.w + u.w + bv.w, 0.f);

            float s1 = vx + vy + vz + vw;
            float s2 = vx * vx + vy * vy + vz * vz + vw * vw;
            #pragma unroll
            for (int o = 16; o > 0; o >>= 1) {
                s1 += __shfl_xor_sync(0xFFFFFFFFu, s1, o);
                s2 += __shfl_xor_sync(0xFFFFFFFFu, s2, o);
            }
            float mu  = s1 * (1.f / 128.f);
            float var = s2 * (1.f / 128.f) - mu * mu;
            float is  = rsqrtf(var + 1e-6f);
            ax += (vx - mu) * is * ga.x + be.x;
            ay += (vy - mu) * is * ga.y + be.y;
            az += (vz - mu) * is * ga.z + be.z;
            aw += (vw - mu) * is * ga.w + be.w;
        }

        sacc[wid * 128 + lane * 4 + 0] = ax;
        sacc[wid * 128 + lane * 4 + 1] = ay;
        sacc[wid * 128 + lane * 4 + 2] = az;
        sacc[wid * 128 + lane * 4 + 3] = aw;
        __syncthreads();
        if (tid < 128) {
            float s = 0.f;
            #pragma unroll
            for (int ww = 0; ww < 8; ww++) s += sacc[ww * 128 + tid];
            atomicAdd(&g_gsum[tid], s);
        }
    }
}

// ---------------------------------------------------------------------------
// CSR build: histogram -> 3-phase multi-block scan -> scatter
// ---------------------------------------------------------------------------
__global__ void k_hist(const int* __restrict__ dst, int e) {
    int i = blockIdx.x * blockDim.x + threadIdx.x;
    if (i < e) atomicAdd(&g_deg[dst[i]], 1);
}

// Phase 1: per-block exclusive scan; partials -> g_off, block total -> g_bsum
__global__ void __launch_bounds__(SCAN_B) k_scan1(int n) {
    __shared__ int wsum[32];
    int tid = threadIdx.x;
    int lane = tid & 31, wd = tid >> 5;
    int i = blockIdx.x * SCAN_B + tid;
    int d = (i < n) ? g_deg[i] : 0;
    int v = d;
    #pragma unroll
    for (int o = 1; o < 32; o <<= 1) {
        int t = __shfl_up_sync(0xFFFFFFFFu, v, o);
        if (lane >= o) v += t;
    }
    if (lane == 31) wsum[wd] = v;
    __syncthreads();
    if (wd == 0) {
        int w = wsum[lane];
        #pragma unroll
        for (int o = 1; o < 32; o <<= 1) {
            int t = __shfl_up_sync(0xFFFFFFFFu, w, o);
            if (lane >= o) w += t;
        }
        wsum[lane] = w;
    }
    __syncthreads();
    int excl = v - d + (wd ? wsum[wd - 1] : 0);
    if (i < n) g_off[i] = excl;
    if (tid == SCAN_B - 1) g_bsum[blockIdx.x] = excl + d;
}

// Phase 2: scan the block totals (nb <= MAXBLK <= 64); also zero g_gsum
__global__ void k_scan2(int nb) {
    int tid = threadIdx.x;
    if (tid < 64) {
        int v = (tid < nb) ? g_bsum[tid] : 0;
        int lane = tid & 31, wd = tid >> 5;
        __shared__ int lo_total;
        #pragma unroll
        for (int o = 1; o < 32; o <<= 1) {
            int t = __shfl_up_sync(0xFFFFFFFFu, v, o);
            if (lane >= o) v += t;
        }
        if (wd == 0 && lane == 31) lo_total = v;
        __syncthreads();
        if (wd == 1) v += lo_total;
        if (tid < nb) g_bsum[tid] = v;   // inclusive scan of totals
    }
    if (tid < 128) g_gsum[tid] = 0.f;
}

// Phase 3: add block offsets; finalize g_off and g_cur
__global__ void __launch_bounds__(SCAN_B) k_scan3(int n) {
    int b = blockIdx.x;
    int i = b * SCAN_B + threadIdx.x;
    if (i >= n) return;
    int add = (b > 0) ? g_bsum[b - 1] : 0;
    int o = g_off[i] + add;
    g_off[i] = o;
    g_cur[i] = o;
}

__global__ void k_scatter(const int* __restrict__ src, const int* __restrict__ dst, int e) {
    int i = blockIdx.x * blockDim.x + threadIdx.x;
    if (i < e) {
        int pos = atomicAdd(&g_cur[dst[i]], 1);
        g_elist[pos] = src[i];
    }
}

// ---------------------------------------------------------------------------
// Gather: warp per node d. pooled[d] = mean over edges of relu(a[src]+b[d]).
// fp16 a rows (256B random, L2-resident); 2-deep software pipeline for MLP.
// ---------------------------------------------------------------------------
__global__ void __launch_bounds__(256) k_gather(int n) {
    int w = (blockIdx.x * blockDim.x + threadIdx.x) >> 5;
    if (w >= n) return;
    int lane = threadIdx.x & 31;
    int off = g_off[w], deg = g_deg[w];

    float2 vb01 = __half22float2(__ldg(g_b + (size_t)w * 64 + lane * 2));
    float2 vb23 = __half22float2(__ldg(g_b + (size_t)w * 64 + lane * 2 + 1));
    float ax = 0.f, ay = 0.f, az = 0.f, aw = 0.f;

    if (deg > 0) {
        int s = g_elist[off];
        half2 pa0 = __ldg(g_a + (size_t)s * 64 + lane * 2);
        half2 pa1 = __ldg(g_a + (size_t)s * 64 + lane * 2 + 1);
        for (int j = 0; j < deg; j++) {
            int s2 = (j + 1 < deg) ? g_elist[off + j + 1] : 0;
            half2 na0 = __ldg(g_a + (size_t)s2 * 64 + lane * 2);
            half2 na1 = __ldg(g_a + (size_t)s2 * 64 + lane * 2 + 1);
            float2 a01 = __half22float2(pa0);
            float2 a23 = __half22float2(pa1);
            ax += fmaxf(a01.x + vb01.x, 0.f);
            ay += fmaxf(a01.y + vb01.y, 0.f);
            az += fmaxf(a23.x + vb23.x, 0.f);
            aw += fmaxf(a23.y + vb23.y, 0.f);
            pa0 = na0; pa1 = na1;
        }
    }
    float rc = 1.0f / (float)max(deg, 1);
    half2 o01 = __floats2half2_rn(ax * rc, ay * rc);
    half2 o23 = __floats2half2_rn(az * rc, aw * rc);
    g_pool[(size_t)w * 64 + lane * 2]     = o01;
    g_pool[(size_t)w * 64 + lane * 2 + 1] = o23;
}

// ---------------------------------------------------------------------------
__global__ void k_final(const float* __restrict__ Wd, const float* __restrict__ bd,
                        float* __restrict__ out, int n) {
    int o = threadIdx.x;
    if (o >= 32) return;
    float s = 0.f;
    #pragma unroll
    for (int c = 0; c < 128; c++) s += g_gsum[c] * Wd[c * 32 + o];
    out[o] = s / (float)n + bd[o];
}

// ---------------------------------------------------------------------------
extern "C" void kernel_launch(void* const* d_in, const int* in_sizes, int n_in,
                              void* d_out, int out_size) {
    const float* x     = (const float*)d_in[0];
    const int*   esrc  = (const int*)d_in[1];
    const int*   edst  = (const int*)d_in[2];
    const float* Wp    = (const float*)d_in[3];
    const float* bp    = (const float*)d_in[4];
    const float* Wm    = (const float*)d_in[5];
    const float* bm    = (const float*)d_in[6];
    const float* Wu    = (const float*)d_in[7];
    const float* bu    = (const float*)d_in[8];
    const float* gamma = (const float*)d_in[9];
    const float* beta  = (const float*)d_in[10];
    const float* Wd    = (const float*)d_in[11];
    const float* bd    = (const float*)d_in[12];
    float* out = (float*)d_out;

    int n = in_sizes[0] / 128;
    int e = in_sizes[1];
    int rb = (n + 127) / 128;
    int nb = (n + SCAN_B - 1) / SCAN_B;

    cudaFuncSetAttribute(k_gemm_h, cudaFuncAttributeMaxDynamicSharedMemorySize, GSM_SZ);

    // combined weights + deg zero
    k_prep<<<(n + 255) / 256, 256>>>(Wp, bp, Wm, bm, Wu, n);
    // hc | a | b from one GEMM pass
    k_gemm_h<<<dim3(3, rb), 256, GSM_SZ>>>(x, nullptr, nullptr, nullptr, nullptr, n, 0);
    // CSR build + gather (segment mean)
    k_hist<<<(e + 255) / 256, 256>>>(edst, e);
    k_scan1<<<nb, SCAN_B>>>(n);
    k_scan2<<<1, 128>>>(nb);
    k_scan3<<<nb, SCAN_B>>>(n);
    k_scatter<<<(e + 255) / 256, 256>>>(esrc, edst, e);
    k_gather<<<(n * 32 + 255) / 256, 256>>>(n);
    // upd-GEMM fused with relu+LN+graph-pool
    k_gemm_h<<<dim3(1, rb), 256, GSM_SZ>>>(nullptr, Wu + 16384, bu, gamma, beta, n, 1);
    k_final<<<1, 32>>>(Wd, bd, out, n);
}

// round 14
// speedup vs baseline: 2.1513x; 1.0962x over previous
#include <cuda_runtime.h>
#include <cuda_fp16.h>
#include <mma.h>
#include <cstdint>

using namespace nvcuda;

// Problem constants: N=50000, E=640000, D=H=128, OUT=32
#define MAXN 50000
#define MAXE 640000
#define SCAN_B 1024
#define MAXBLK 64

// Scratch (device globals — no allocation allowed)
__device__ float g_W3[128 * 384];     // [Wp+Wp@WuA | Wp@WmA | Wp@WmB]
__device__ float g_b3[384];           // [bp+bp@WuA | bp@WmA | bp@WmB+bm]
__device__ float g_Y[MAXN * 128];     // hc = h0 + c   fp32
__device__ half2 g_a[MAXN * 64];      // a = h0@WmA                fp16
__device__ half2 g_b[MAXN * 64];      // b = h0@WmB + bm           fp16
__device__ half2 g_pool[MAXN * 64];   // pooled mean               fp16
__device__ float g_gsum[128];         // graph-level sum of normalized hn
__device__ int   g_deg[MAXN];         // per-dst degree
__device__ int   g_off[MAXN];         // CSR offsets
__device__ int   g_cur[MAXN];         // scatter cursors
__device__ int   g_elist[MAXE];       // src ids grouped by dst
__device__ int   g_bsum[MAXBLK];      // per-block scan totals

// ---------------------------------------------------------------------------
__global__ void k_zero_deg(int n) {
    int i = blockIdx.x * blockDim.x + threadIdx.x;
    if (i < n) g_deg[i] = 0;
}

// ---------------------------------------------------------------------------
// Combined weight build (weights only — deg zero is separate for stream fork).
// W3 col-blocks: 0: Wp + Wp@WuA, 1: Wp@WmA, 2: Wp@WmB
// b3           : 0: bp + bp@WuA, 1: bp@WmA, 2: bp@WmB + bm
// ---------------------------------------------------------------------------
__global__ void k_prepw(const float* __restrict__ Wp, const float* __restrict__ bp,
                        const float* __restrict__ Wm, const float* __restrict__ bm,
                        const float* __restrict__ Wu) {
    int idx = blockIdx.x * blockDim.x + threadIdx.x;
    if (idx < 3 * 16384) {
        int blk = idx >> 14;
        int rem = idx & 16383;
        int i = rem >> 7, jj = rem & 127;
        const float* M = (blk == 0) ? Wu : ((blk == 1) ? Wm : Wm + 16384);
        float s = (blk == 0) ? Wp[i * 128 + jj] : 0.f;
        for (int k = 0; k < 128; k++) s += Wp[i * 128 + k] * M[k * 128 + jj];
        g_W3[i * 384 + blk * 128 + jj] = s;
    }
    if (idx < 384) {
        int blk = idx >> 7, jj = idx & 127;
        const float* M = (blk == 0) ? Wu : ((blk == 1) ? Wm : Wm + 16384);
        float s = (blk == 0) ? bp[jj] : ((blk == 2) ? bm[jj] : 0.f);
        for (int k = 0; k < 128; k++) s += bp[k] * M[k * 128 + jj];
        g_b3[idx] = s;
    }
}

// ---------------------------------------------------------------------------
// fp16 wmma GEMM, CTA = 128x128 tile, K=128 in smem.
// mode 0 (grid.x=3): Y = x @ W3 + b3; blk 0->g_Y hc (fp32), 1->g_a, 2->g_b (fp16)
// mode 1 (grid.x=1): fused upd-GEMM (pool fp16 @ WuB) + relu + LN + graph-pool
// ---------------------------------------------------------------------------
#define LDH 136
#define LDC 132
#define SM_A_BYTES (128 * LDH * 2)          // 34816
#define SACC_OFF   (2 * SM_A_BYTES)         // 69632 (Cs ends at 67584)
#define GSM_SZ     (SACC_OFF + 4096)        // 73728

__global__ void __launch_bounds__(256, 2) k_gemm_h(const float* __restrict__ Xext,
                                                   const float* __restrict__ Wext,
                                                   const float* __restrict__ biasExt,
                                                   const float* __restrict__ gamma,
                                                   const float* __restrict__ beta,
                                                   int n, int mode) {
    extern __shared__ __align__(16) char smw[];
    half*  As = (half*)smw;
    half*  Bs = (half*)(smw + SM_A_BYTES);
    float* Cs = (float*)smw;                    // overlaps A+B (after sync)
    float* sacc = (float*)(smw + SACC_OFF);     // [8][128] LN partials

    const float* W    = mode ? Wext   : g_W3;
    const float* bias = mode ? biasExt : g_b3;
    const int wp4     = mode ? 32 : 96;    // W row pitch (float4)
    const int rowBase = blockIdx.y * 128;
    const int cb4     = blockIdx.x * 32;   // W column base (float4)

    const int tid = threadIdx.x;
    const int wid = tid >> 5;
    const int lane = tid & 31;

    // ---- Fill A and B tiles ----
    const float4* X4 = (const float4*)Xext;
    const float4* W4 = (const float4*)W;
    const uint2*  P2 = (const uint2*)g_pool;
    #pragma unroll
    for (int it = 0; it < 16; it++) {
        int i = tid + it * 256;
        int m = i >> 5, c4 = i & 31;
        int row = rowBase + m;
        if (mode == 0) {
            float4 v = make_float4(0.f, 0.f, 0.f, 0.f);
            if (row < n) v = X4[(size_t)row * 32 + c4];
            half2* da = (half2*)&As[m * LDH + c4 * 4];
            da[0] = __floats2half2_rn(v.x, v.y);
            da[1] = __floats2half2_rn(v.z, v.w);
        } else {
            uint2 u = make_uint2(0u, 0u);
            if (row < n) u = __ldg(P2 + (size_t)row * 32 + c4);
            *(uint2*)&As[m * LDH + c4 * 4] = u;      // raw fp16 copy
        }
        float4 w = W4[(size_t)m * wp4 + cb4 + c4];
        half2* db = (half2*)&Bs[m * LDH + c4 * 4];
        db[0] = __floats2half2_rn(w.x, w.y);
        db[1] = __floats2half2_rn(w.z, w.w);
    }
    __syncthreads();

    // ---- MMA main loop ----
    const int wrow = (wid & 3) * 32;
    const int wcol = (wid >> 2) * 64;

    wmma::fragment<wmma::accumulator, 16, 16, 16, float> acc[2][4];
    #pragma unroll
    for (int r = 0; r < 2; r++)
        #pragma unroll
        for (int c = 0; c < 4; c++) wmma::fill_fragment(acc[r][c], 0.0f);

    #pragma unroll
    for (int kk = 0; kk < 8; kk++) {
        wmma::fragment<wmma::matrix_a, 16, 16, 16, half, wmma::row_major> af[2];
        wmma::fragment<wmma::matrix_b, 16, 16, 16, half, wmma::row_major> bf[4];
        #pragma unroll
        for (int r = 0; r < 2; r++)
            wmma::load_matrix_sync(af[r], &As[(wrow + r * 16) * LDH + kk * 16], LDH);
        #pragma unroll
        for (int c = 0; c < 4; c++)
            wmma::load_matrix_sync(bf[c], &Bs[(kk * 16) * LDH + wcol + c * 16], LDH);
        #pragma unroll
        for (int r = 0; r < 2; r++)
            #pragma unroll
            for (int c = 0; c < 4; c++)
                wmma::mma_sync(acc[r][c], af[r], bf[c], acc[r][c]);
    }

    // ---- Stage C (fp32) into smem ----
    __syncthreads();
    #pragma unroll
    for (int r = 0; r < 2; r++)
        #pragma unroll
        for (int c = 0; c < 4; c++)
            wmma::store_matrix_sync(&Cs[(wrow + r * 16) * LDC + wcol + c * 16],
                                    acc[r][c], LDC, wmma::mem_row_major);
    __syncthreads();

    const float4* b4 = (const float4*)bias;

    if (mode == 0) {
        const int blk = blockIdx.x;
        #pragma unroll
        for (int it = 0; it < 16; it++) {
            int i = tid + it * 256;
            int m = i >> 5, c4 = i & 31;
            int row = rowBase + m;
            if (row >= n) continue;
            float4 v = *(float4*)&Cs[m * LDC + c4 * 4];
            float4 bv = b4[cb4 + c4];
            v.x += bv.x; v.y += bv.y; v.z += bv.z; v.w += bv.w;
            if (blk == 0) {
                ((float4*)g_Y)[(size_t)row * 32 + c4] = v;            // hc fp32
            } else {
                half2 h0 = __floats2half2_rn(v.x, v.y);
                half2 h1 = __floats2half2_rn(v.z, v.w);
                half2* dstp = (blk == 1) ? g_a : g_b;
                dstp[(size_t)row * 64 + c4 * 2]     = h0;
                dstp[(size_t)row * 64 + c4 * 2 + 1] = h1;
            }
        }
    } else {
        // ---- Fused: upd + relu(hc+upd+bu) + LayerNorm + graph-pool partials ----
        float4 ga = ((const float4*)gamma)[lane];
        float4 be = ((const float4*)beta)[lane];
        float ax = 0.f, ay = 0.f, az = 0.f, aw = 0.f;
        float4 bv = b4[lane];   // bu

        #pragma unroll
        for (int it = 0; it < 16; it++) {
            int m = wid + it * 8;             // one warp <-> one row
            int row = rowBase + m;
            if (row >= n) continue;
            float4 u  = *(float4*)&Cs[m * LDC + lane * 4];
            float4 hc = ((const float4*)g_Y)[(size_t)row * 32 + lane];
            float vx = fmaxf(hc.x + u.x + bv.x, 0.f);
            float vy = fmaxf(hc.y + u.y + bv.y, 0.f);
            float vz = fmaxf(hc.z + u.z + bv.z, 0.f);
            float vw = fmaxf(hc.w + u.w + bv.w, 0.f);

            float s1 = vx + vy + vz + vw;
            float s2 = vx * vx + vy * vy + vz * vz + vw * vw;
            #pragma unroll
            for (int o = 16; o > 0; o >>= 1) {
                s1 += __shfl_xor_sync(0xFFFFFFFFu, s1, o);
                s2 += __shfl_xor_sync(0xFFFFFFFFu, s2, o);
            }
            float mu  = s1 * (1.f / 128.f);
            float var = s2 * (1.f / 128.f) - mu * mu;
            float is  = rsqrtf(var + 1e-6f);
            ax += (vx - mu) * is * ga.x + be.x;
            ay += (vy - mu) * is * ga.y + be.y;
            az += (vz - mu) * is * ga.z + be.z;
            aw += (vw - mu) * is * ga.w + be.w;
        }

        sacc[wid * 128 + lane * 4 + 0] = ax;
        sacc[wid * 128 + lane * 4 + 1] = ay;
        sacc[wid * 128 + lane * 4 + 2] = az;
        sacc[wid * 128 + lane * 4 + 3] = aw;
        __syncthreads();
        if (tid < 128) {
            float s = 0.f;
            #pragma unroll
            for (int ww = 0; ww < 8; ww++) s += sacc[ww * 128 + tid];
            atomicAdd(&g_gsum[tid], s);
        }
    }
}

// ---------------------------------------------------------------------------
// CSR build: histogram -> 3-phase multi-block scan -> scatter
// ---------------------------------------------------------------------------
__global__ void k_hist(const int* __restrict__ dst, int e) {
    int i = blockIdx.x * blockDim.x + threadIdx.x;
    if (i < e) atomicAdd(&g_deg[dst[i]], 1);
}

// Phase 1: per-block exclusive scan; partials -> g_off, block total -> g_bsum
__global__ void __launch_bounds__(SCAN_B) k_scan1(int n) {
    __shared__ int wsum[32];
    int tid = threadIdx.x;
    int lane = tid & 31, wd = tid >> 5;
    int i = blockIdx.x * SCAN_B + tid;
    int d = (i < n) ? g_deg[i] : 0;
    int v = d;
    #pragma unroll
    for (int o = 1; o < 32; o <<= 1) {
        int t = __shfl_up_sync(0xFFFFFFFFu, v, o);
        if (lane >= o) v += t;
    }
    if (lane == 31) wsum[wd] = v;
    __syncthreads();
    if (wd == 0) {
        int w = wsum[lane];
        #pragma unroll
        for (int o = 1; o < 32; o <<= 1) {
            int t = __shfl_up_sync(0xFFFFFFFFu, w, o);
            if (lane >= o) w += t;
        }
        wsum[lane] = w;
    }
    __syncthreads();
    int excl = v - d + (wd ? wsum[wd - 1] : 0);
    if (i < n) g_off[i] = excl;
    if (tid == SCAN_B - 1) g_bsum[blockIdx.x] = excl + d;
}

// Phase 2: scan the block totals (nb <= MAXBLK <= 64); also zero g_gsum
__global__ void k_scan2(int nb) {
    int tid = threadIdx.x;
    if (tid < 64) {
        int v = (tid < nb) ? g_bsum[tid] : 0;
        int lane = tid & 31, wd = tid >> 5;
        __shared__ int lo_total;
        #pragma unroll
        for (int o = 1; o < 32; o <<= 1) {
            int t = __shfl_up_sync(0xFFFFFFFFu, v, o);
            if (lane >= o) v += t;
        }
        if (wd == 0 && lane == 31) lo_total = v;
        __syncthreads();
        if (wd == 1) v += lo_total;
        if (tid < nb) g_bsum[tid] = v;   // inclusive scan of totals
    }
    if (tid < 128) g_gsum[tid] = 0.f;
}

// Phase 3: add block offsets; finalize g_off and g_cur
__global__ void __launch_bounds__(SCAN_B) k_scan3(int n) {
    int b = blockIdx.x;
    int i = b * SCAN_B + threadIdx.x;
    if (i >= n) return;
    int add = (b > 0) ? g_bsum[b - 1] : 0;
    int o = g_off[i] + add;
    g_off[i] = o;
    g_cur[i] = o;
}

__global__ void k_scatter(const int* __restrict__ src, const int* __restrict__ dst, int e) {
    int i = blockIdx.x * blockDim.x + threadIdx.x;
    if (i < e) {
        int pos = atomicAdd(&g_cur[dst[i]], 1);
        g_elist[pos] = src[i];
    }
}

// ---------------------------------------------------------------------------
// Gather: warp per node d. pooled[d] = mean over edges of relu(a[src]+b[d]).
// fp16 a rows (256B random, L2-resident); 2-deep software pipeline for MLP.
// ---------------------------------------------------------------------------
__global__ void __launch_bounds__(256) k_gather(int n) {
    int w = (blockIdx.x * blockDim.x + threadIdx.x) >> 5;
    if (w >= n) return;
    int lane = threadIdx.x & 31;
    int off = g_off[w], deg = g_deg[w];

    float2 vb01 = __half22float2(__ldg(g_b + (size_t)w * 64 + lane * 2));
    float2 vb23 = __half22float2(__ldg(g_b + (size_t)w * 64 + lane * 2 + 1));
    float ax = 0.f, ay = 0.f, az = 0.f, aw = 0.f;

    if (deg > 0) {
        int s = g_elist[off];
        half2 pa0 = __ldg(g_a + (size_t)s * 64 + lane * 2);
        half2 pa1 = __ldg(g_a + (size_t)s * 64 + lane * 2 + 1);
        for (int j = 0; j < deg; j++) {
            int s2 = (j + 1 < deg) ? g_elist[off + j + 1] : 0;
            half2 na0 = __ldg(g_a + (size_t)s2 * 64 + lane * 2);
            half2 na1 = __ldg(g_a + (size_t)s2 * 64 + lane * 2 + 1);
            float2 a01 = __half22float2(pa0);
            float2 a23 = __half22float2(pa1);
            ax += fmaxf(a01.x + vb01.x, 0.f);
            ay += fmaxf(a01.y + vb01.y, 0.f);
            az += fmaxf(a23.x + vb23.x, 0.f);
            aw += fmaxf(a23.y + vb23.y, 0.f);
            pa0 = na0; pa1 = na1;
        }
    }
    float rc = 1.0f / (float)max(deg, 1);
    half2 o01 = __floats2half2_rn(ax * rc, ay * rc);
    half2 o23 = __floats2half2_rn(az * rc, aw * rc);
    g_pool[(size_t)w * 64 + lane * 2]     = o01;
    g_pool[(size_t)w * 64 + lane * 2 + 1] = o23;
}

// ---------------------------------------------------------------------------
__global__ void k_final(const float* __restrict__ Wd, const float* __restrict__ bd,
                        float* __restrict__ out, int n) {
    int o = threadIdx.x;
    if (o >= 32) return;
    float s = 0.f;
    #pragma unroll
    for (int c = 0; c < 128; c++) s += g_gsum[c] * Wd[c * 32 + o];
    out[o] = s / (float)n + bd[o];
}

// ---------------------------------------------------------------------------
extern "C" void kernel_launch(void* const* d_in, const int* in_sizes, int n_in,
                              void* d_out, int out_size) {
    const float* x     = (const float*)d_in[0];
    const int*   esrc  = (const int*)d_in[1];
    const int*   edst  = (const int*)d_in[2];
    const float* Wp    = (const float*)d_in[3];
    const float* bp    = (const float*)d_in[4];
    const float* Wm    = (const float*)d_in[5];
    const float* bm    = (const float*)d_in[6];
    const float* Wu    = (const float*)d_in[7];
    const float* bu    = (const float*)d_in[8];
    const float* gamma = (const float*)d_in[9];
    const float* beta  = (const float*)d_in[10];
    const float* Wd    = (const float*)d_in[11];
    const float* bd    = (const float*)d_in[12];
    float* out = (float*)d_out;

    int n = in_sizes[0] / 128;
    int e = in_sizes[1];
    int rb = (n + 127) / 128;
    int nb = (n + SCAN_B - 1) / SCAN_B;

    cudaFuncSetAttribute(k_gemm_h, cudaFuncAttributeMaxDynamicSharedMemorySize, GSM_SZ);

    // Fork resources (host objects; created per call, intentionally not
    // destroyed — destroying a stream mid-capture would invalidate capture).
    cudaStream_t side;
    cudaEvent_t evf, evj;
    cudaStreamCreateWithFlags(&side, cudaStreamNonBlocking);
    cudaEventCreateWithFlags(&evf, cudaEventDisableTiming);
    cudaEventCreateWithFlags(&evj, cudaEventDisableTiming);

    // main: zero degrees, then fork
    k_zero_deg<<<(n + 1023) / 1024, 1024>>>(n);
    cudaEventRecord(evf, 0);
    cudaStreamWaitEvent(side, evf, 0);

    // side: CSR build (depends only on edges + deg zero)
    k_hist<<<(e + 255) / 256, 256, 0, side>>>(edst, e);
    k_scan1<<<nb, SCAN_B, 0, side>>>(n);
    k_scan2<<<1, 128, 0, side>>>(nb);
    k_scan3<<<nb, SCAN_B, 0, side>>>(n);
    k_scatter<<<(e + 255) / 256, 256, 0, side>>>(esrc, edst, e);
    cudaEventRecord(evj, side);

    // main (concurrent with side): weights, then hc | a | b GEMM
    k_prepw<<<192, 256>>>(Wp, bp, Wm, bm, Wu);
    k_gemm_h<<<dim3(3, rb), 256, GSM_SZ>>>(x, nullptr, nullptr, nullptr, nullptr, n, 0);

    // join: gather needs elist (side) + a/b (main)
    cudaStreamWaitEvent(0, evj, 0);
    k_gather<<<(n * 32 + 255) / 256, 256>>>(n);
    // upd-GEMM fused with relu+LN+graph-pool
    k_gemm_h<<<dim3(1, rb), 256, GSM_SZ>>>(nullptr, Wu + 16384, bu, gamma, beta, n, 1);
    k_final<<<1, 32>>>(Wd, bd, out, n);
}

// round 15
// speedup vs baseline: 2.8991x; 1.3476x over previous
#include <cuda_runtime.h>
#include <cuda_fp16.h>
#include <mma.h>
#include <cstdint>

using namespace nvcuda;

// Problem constants: N=50000, E=640000, D=H=128, OUT=32
#define MAXN 50000
#define MAXE 640000
#define SCAN_B 1024
#define MAXBLK 64

// Scratch (device globals — no allocation allowed)
__device__ half  g_W3h[3 * 16384];    // fp16 blocked: [Wp+Wp@WuA][Wp@WmA][Wp@WmB]
__device__ float g_b3[384];           // [bp+bp@WuA | bp@WmA | bp@WmB+bm]
__device__ float g_Y[MAXN * 128];     // hc = h0 + c   fp32
__device__ half2 g_a[MAXN * 64];      // a = h0@WmA                fp16
__device__ half2 g_b[MAXN * 64];      // b = h0@WmB + bm           fp16
__device__ half2 g_pool[MAXN * 64];   // pooled mean               fp16
__device__ float g_gsum[128];         // graph-level sum of normalized hn
__device__ int   g_deg[MAXN];         // per-dst degree
__device__ int   g_off[MAXN];         // CSR offsets
__device__ int   g_cur[MAXN];         // scatter cursors
__device__ int   g_elist[MAXE];       // src ids grouped by dst
__device__ int   g_bsum[MAXBLK];      // per-block scan totals

#define LDH 136
#define LDC 132
#define SM_A_BYTES (128 * LDH * 2)          // 34816
// gemm0: As persistent + (Bs | Cs) overlapped region
#define GSM0 (SM_A_BYTES + 128 * LDC * 4)   // 34816 + 67584 = 102400
// gemm1: As+Bs, Cs overlaps both, sacc after
#define SACC_OFF (2 * SM_A_BYTES)           // 69632
#define GSM1 (SACC_OFF + 4096)              // 73728

// ---------------------------------------------------------------------------
__global__ void k_zero_deg(int n) {
    int i = blockIdx.x * blockDim.x + threadIdx.x;
    if (i < n) g_deg[i] = 0;
}

// ---------------------------------------------------------------------------
// Combined weight build -> fp16 blocked layout.
// blk 0: Wp + Wp@WuA, 1: Wp@WmA, 2: Wp@WmB ; bias fp32 alongside.
// ---------------------------------------------------------------------------
__global__ void k_prepw(const float* __restrict__ Wp, const float* __restrict__ bp,
                        const float* __restrict__ Wm, const float* __restrict__ bm,
                        const float* __restrict__ Wu) {
    int idx = blockIdx.x * blockDim.x + threadIdx.x;
    if (idx < 3 * 16384) {
        int blk = idx >> 14;
        int rem = idx & 16383;
        int i = rem >> 7, jj = rem & 127;
        const float* M = (blk == 0) ? Wu : ((blk == 1) ? Wm : Wm + 16384);
        float s = (blk == 0) ? Wp[i * 128 + jj] : 0.f;
        for (int k = 0; k < 128; k++) s += Wp[i * 128 + k] * M[k * 128 + jj];
        g_W3h[blk * 16384 + i * 128 + jj] = __float2half(s);
    }
    if (idx < 384) {
        int blk = idx >> 7, jj = idx & 127;
        const float* M = (blk == 0) ? Wu : ((blk == 1) ? Wm : Wm + 16384);
        float s = (blk == 0) ? bp[jj] : ((blk == 2) ? bm[jj] : 0.f);
        for (int k = 0; k < 128; k++) s += bp[k] * M[k * 128 + jj];
        g_b3[idx] = s;
    }
}

// ---------------------------------------------------------------------------
// gemm0: one CTA per 128-row block; A filled once (fp32->fp16), then loop over
// the 3 fp16 weight column-blocks: fill B (raw copy) -> MMA -> epilogue.
// Outputs: cb 0 -> g_Y hc (fp32), 1 -> g_a (fp16), 2 -> g_b (fp16).
// ---------------------------------------------------------------------------
__global__ void __launch_bounds__(256, 2) k_gemm0(const float* __restrict__ X, int n) {
    extern __shared__ __align__(16) char smw[];
    half*  As = (half*)smw;
    half*  Bs = (half*)(smw + SM_A_BYTES);
    float* Cs = (float*)(smw + SM_A_BYTES);     // overlaps Bs (phased by syncs)

    const int tid = threadIdx.x;
    const int wid = tid >> 5;
    const int rowBase = blockIdx.x * 128;

    // ---- Fill A once ----
    const float4* X4 = (const float4*)X;
    #pragma unroll
    for (int it = 0; it < 16; it++) {
        int i = tid + it * 256;
        int m = i >> 5, c4 = i & 31;
        int row = rowBase + m;
        float4 v = make_float4(0.f, 0.f, 0.f, 0.f);
        if (row < n) v = X4[(size_t)row * 32 + c4];
        half2* da = (half2*)&As[m * LDH + c4 * 4];
        da[0] = __floats2half2_rn(v.x, v.y);
        da[1] = __floats2half2_rn(v.z, v.w);
    }

    const int wrow = (wid & 3) * 32;
    const int wcol = (wid >> 2) * 64;
    const float4* b4 = (const float4*)g_b3;

    for (int cb = 0; cb < 3; cb++) {
        __syncthreads();   // A ready (cb=0) / previous epilogue done reading Cs
        // ---- Fill B: raw fp16 copy, 32KB ----
        const uint4* Wsrc = (const uint4*)(g_W3h + cb * 16384);
        #pragma unroll
        for (int it = 0; it < 8; it++) {
            int i = tid + it * 256;
            int r = i >> 4, c16 = i & 15;
            *(uint4*)&Bs[r * LDH + c16 * 8] = Wsrc[r * 16 + c16];
        }
        __syncthreads();

        // ---- MMA ----
        wmma::fragment<wmma::accumulator, 16, 16, 16, float> acc[2][4];
        #pragma unroll
        for (int r = 0; r < 2; r++)
            #pragma unroll
            for (int c = 0; c < 4; c++) wmma::fill_fragment(acc[r][c], 0.0f);
        #pragma unroll
        for (int kk = 0; kk < 8; kk++) {
            wmma::fragment<wmma::matrix_a, 16, 16, 16, half, wmma::row_major> af[2];
            wmma::fragment<wmma::matrix_b, 16, 16, 16, half, wmma::row_major> bf[4];
            #pragma unroll
            for (int r = 0; r < 2; r++)
                wmma::load_matrix_sync(af[r], &As[(wrow + r * 16) * LDH + kk * 16], LDH);
            #pragma unroll
            for (int c = 0; c < 4; c++)
                wmma::load_matrix_sync(bf[c], &Bs[(kk * 16) * LDH + wcol + c * 16], LDH);
            #pragma unroll
            for (int r = 0; r < 2; r++)
                #pragma unroll
                for (int c = 0; c < 4; c++)
                    wmma::mma_sync(acc[r][c], af[r], bf[c], acc[r][c]);
        }
        __syncthreads();   // all warps done reading Bs before Cs overwrite

        #pragma unroll
        for (int r = 0; r < 2; r++)
            #pragma unroll
            for (int c = 0; c < 4; c++)
                wmma::store_matrix_sync(&Cs[(wrow + r * 16) * LDC + wcol + c * 16],
                                        acc[r][c], LDC, wmma::mem_row_major);
        __syncthreads();

        // ---- Epilogue for this column block ----
        #pragma unroll
        for (int it = 0; it < 16; it++) {
            int i = tid + it * 256;
            int m = i >> 5, c4 = i & 31;
            int row = rowBase + m;
            if (row >= n) continue;
            float4 v = *(float4*)&Cs[m * LDC + c4 * 4];
            float4 bv = b4[cb * 32 + c4];
            v.x += bv.x; v.y += bv.y; v.z += bv.z; v.w += bv.w;
            if (cb == 0) {
                ((float4*)g_Y)[(size_t)row * 32 + c4] = v;            // hc fp32
            } else {
                half2 h0 = __floats2half2_rn(v.x, v.y);
                half2 h1 = __floats2half2_rn(v.z, v.w);
                half2* dstp = (cb == 1) ? g_a : g_b;
                dstp[(size_t)row * 64 + c4 * 2]     = h0;
                dstp[(size_t)row * 64 + c4 * 2 + 1] = h1;
            }
        }
    }
}

// ---------------------------------------------------------------------------
// gemm1: fused upd-GEMM (pool fp16 @ WuB) + relu + LayerNorm + graph-pool.
// ---------------------------------------------------------------------------
__global__ void __launch_bounds__(256, 2) k_gemm1(const float* __restrict__ Wext,
                                                  const float* __restrict__ biasExt,
                                                  const float* __restrict__ gamma,
                                                  const float* __restrict__ beta,
                                                  int n) {
    extern __shared__ __align__(16) char smw[];
    half*  As = (half*)smw;
    half*  Bs = (half*)(smw + SM_A_BYTES);
    float* Cs = (float*)smw;                    // overlaps A+B (after sync)
    float* sacc = (float*)(smw + SACC_OFF);     // [8][128] LN partials

    const int rowBase = blockIdx.x * 128;
    const int tid = threadIdx.x;
    const int wid = tid >> 5;
    const int lane = tid & 31;

    // ---- Fill A (raw fp16 pool copy) and B (fp32 Wu -> fp16) ----
    const float4* W4 = (const float4*)Wext;
    const uint2*  P2 = (const uint2*)g_pool;
    #pragma unroll
    for (int it = 0; it < 16; it++) {
        int i = tid + it * 256;
        int m = i >> 5, c4 = i & 31;
        int row = rowBase + m;
        uint2 u = make_uint2(0u, 0u);
        if (row < n) u = __ldg(P2 + (size_t)row * 32 + c4);
        *(uint2*)&As[m * LDH + c4 * 4] = u;
        float4 w = W4[(size_t)m * 32 + c4];
        half2* db = (half2*)&Bs[m * LDH + c4 * 4];
        db[0] = __floats2half2_rn(w.x, w.y);
        db[1] = __floats2half2_rn(w.z, w.w);
    }
    __syncthreads();

    const int wrow = (wid & 3) * 32;
    const int wcol = (wid >> 2) * 64;

    wmma::fragment<wmma::accumulator, 16, 16, 16, float> acc[2][4];
    #pragma unroll
    for (int r = 0; r < 2; r++)
        #pragma unroll
        for (int c = 0; c < 4; c++) wmma::fill_fragment(acc[r][c], 0.0f);

    #pragma unroll
    for (int kk = 0; kk < 8; kk++) {
        wmma::fragment<wmma::matrix_a, 16, 16, 16, half, wmma::row_major> af[2];
        wmma::fragment<wmma::matrix_b, 16, 16, 16, half, wmma::row_major> bf[4];
        #pragma unroll
        for (int r = 0; r < 2; r++)
            wmma::load_matrix_sync(af[r], &As[(wrow + r * 16) * LDH + kk * 16], LDH);
        #pragma unroll
        for (int c = 0; c < 4; c++)
            wmma::load_matrix_sync(bf[c], &Bs[(kk * 16) * LDH + wcol + c * 16], LDH);
        #pragma unroll
        for (int r = 0; r < 2; r++)
            #pragma unroll
            for (int c = 0; c < 4; c++)
                wmma::mma_sync(acc[r][c], af[r], bf[c], acc[r][c]);
    }

    __syncthreads();
    #pragma unroll
    for (int r = 0; r < 2; r++)
        #pragma unroll
        for (int c = 0; c < 4; c++)
            wmma::store_matrix_sync(&Cs[(wrow + r * 16) * LDC + wcol + c * 16],
                                    acc[r][c], LDC, wmma::mem_row_major);
    __syncthreads();

    // ---- Fused: relu(hc+upd+bu) + LayerNorm + graph-pool partials ----
    const float4* b4 = (const float4*)biasExt;
    float4 ga = ((const float4*)gamma)[lane];
    float4 be = ((const float4*)beta)[lane];
    float ax = 0.f, ay = 0.f, az = 0.f, aw = 0.f;
    float4 bv = b4[lane];   // bu

    #pragma unroll
    for (int it = 0; it < 16; it++) {
        int m = wid + it * 8;             // one warp <-> one row
        int row = rowBase + m;
        if (row >= n) continue;
        float4 u  = *(float4*)&Cs[m * LDC + lane * 4];
        float4 hc = ((const float4*)g_Y)[(size_t)row * 32 + lane];
        float vx = fmaxf(hc.x + u.x + bv.x, 0.f);
        float vy = fmaxf(hc.y + u.y + bv.y, 0.f);
        float vz = fmaxf(hc.z + u.z + bv.z, 0.f);
        float vw = fmaxf(hc.w + u.w + bv.w, 0.f);

        float s1 = vx + vy + vz + vw;
        float s2 = vx * vx + vy * vy + vz * vz + vw * vw;
        #pragma unroll
        for (int o = 16; o > 0; o >>= 1) {
            s1 += __shfl_xor_sync(0xFFFFFFFFu, s1, o);
            s2 += __shfl_xor_sync(0xFFFFFFFFu, s2, o);
        }
        float mu  = s1 * (1.f / 128.f);
        float var = s2 * (1.f / 128.f) - mu * mu;
        float is  = rsqrtf(var + 1e-6f);
        ax += (vx - mu) * is * ga.x + be.x;
        ay += (vy - mu) * is * ga.y + be.y;
        az += (vz - mu) * is * ga.z + be.z;
        aw += (vw - mu) * is * ga.w + be.w;
    }

    sacc[wid * 128 + lane * 4 + 0] = ax;
    sacc[wid * 128 + lane * 4 + 1] = ay;
    sacc[wid * 128 + lane * 4 + 2] = az;
    sacc[wid * 128 + lane * 4 + 3] = aw;
    __syncthreads();
    if (tid < 128) {
        float s = 0.f;
        #pragma unroll
        for (int ww = 0; ww < 8; ww++) s += sacc[ww * 128 + tid];
        atomicAdd(&g_gsum[tid], s);
    }
}

// ---------------------------------------------------------------------------
// CSR build: histogram -> 3-phase multi-block scan -> scatter
// ---------------------------------------------------------------------------
__global__ void k_hist(const int* __restrict__ dst, int e) {
    int i = blockIdx.x * blockDim.x + threadIdx.x;
    if (i < e) atomicAdd(&g_deg[dst[i]], 1);
}

__global__ void __launch_bounds__(SCAN_B) k_scan1(int n) {
    __shared__ int wsum[32];
    int tid = threadIdx.x;
    int lane = tid & 31, wd = tid >> 5;
    int i = blockIdx.x * SCAN_B + tid;
    int d = (i < n) ? g_deg[i] : 0;
    int v = d;
    #pragma unroll
    for (int o = 1; o < 32; o <<= 1) {
        int t = __shfl_up_sync(0xFFFFFFFFu, v, o);
        if (lane >= o) v += t;
    }
    if (lane == 31) wsum[wd] = v;
    __syncthreads();
    if (wd == 0) {
        int w = wsum[lane];
        #pragma unroll
        for (int o = 1; o < 32; o <<= 1) {
            int t = __shfl_up_sync(0xFFFFFFFFu, w, o);
            if (lane >= o) w += t;
        }
        wsum[lane] = w;
    }
    __syncthreads();
    int excl = v - d + (wd ? wsum[wd - 1] : 0);
    if (i < n) g_off[i] = excl;
    if (tid == SCAN_B - 1) g_bsum[blockIdx.x] = excl + d;
}

__global__ void k_scan2(int nb) {
    int tid = threadIdx.x;
    if (tid < 64) {
        int v = (tid < nb) ? g_bsum[tid] : 0;
        int lane = tid & 31, wd = tid >> 5;
        __shared__ int lo_total;
        #pragma unroll
        for (int o = 1; o < 32; o <<= 1) {
            int t = __shfl_up_sync(0xFFFFFFFFu, v, o);
            if (lane >= o) v += t;
        }
        if (wd == 0 && lane == 31) lo_total = v;
        __syncthreads();
        if (wd == 1) v += lo_total;
        if (tid < nb) g_bsum[tid] = v;
    }
    if (tid < 128) g_gsum[tid] = 0.f;
}

__global__ void __launch_bounds__(SCAN_B) k_scan3(int n) {
    int b = blockIdx.x;
    int i = b * SCAN_B + threadIdx.x;
    if (i >= n) return;
    int add = (b > 0) ? g_bsum[b - 1] : 0;
    int o = g_off[i] + add;
    g_off[i] = o;
    g_cur[i] = o;
}

__global__ void k_scatter(const int* __restrict__ src, const int* __restrict__ dst, int e) {
    int i = blockIdx.x * blockDim.x + threadIdx.x;
    if (i < e) {
        int pos = atomicAdd(&g_cur[dst[i]], 1);
        g_elist[pos] = src[i];
    }
}

// ---------------------------------------------------------------------------
// Gather: warp per node d. pooled[d] = mean over edges of relu(a[src]+b[d]).
// ---------------------------------------------------------------------------
__global__ void __launch_bounds__(256) k_gather(int n) {
    int w = (blockIdx.x * blockDim.x + threadIdx.x) >> 5;
    if (w >= n) return;
    int lane = threadIdx.x & 31;
    int off = g_off[w], deg = g_deg[w];

    float2 vb01 = __half22float2(__ldg(g_b + (size_t)w * 64 + lane * 2));
    float2 vb23 = __half22float2(__ldg(g_b + (size_t)w * 64 + lane * 2 + 1));
    float ax = 0.f, ay = 0.f, az = 0.f, aw = 0.f;

    if (deg > 0) {
        int s = g_elist[off];
        half2 pa0 = __ldg(g_a + (size_t)s * 64 + lane * 2);
        half2 pa1 = __ldg(g_a + (size_t)s * 64 + lane * 2 + 1);
        for (int j = 0; j < deg; j++) {
            int s2 = (j + 1 < deg) ? g_elist[off + j + 1] : 0;
            half2 na0 = __ldg(g_a + (size_t)s2 * 64 + lane * 2);
            half2 na1 = __ldg(g_a + (size_t)s2 * 64 + lane * 2 + 1);
            float2 a01 = __half22float2(pa0);
            float2 a23 = __half22float2(pa1);
            ax += fmaxf(a01.x + vb01.x, 0.f);
            ay += fmaxf(a01.y + vb01.y, 0.f);
            az += fmaxf(a23.x + vb23.x, 0.f);
            aw += fmaxf(a23.y + vb23.y, 0.f);
            pa0 = na0; pa1 = na1;
        }
    }
    float rc = 1.0f / (float)max(deg, 1);
    half2 o01 = __floats2half2_rn(ax * rc, ay * rc);
    half2 o23 = __floats2half2_rn(az * rc, aw * rc);
    g_pool[(size_t)w * 64 + lane * 2]     = o01;
    g_pool[(size_t)w * 64 + lane * 2 + 1] = o23;
}

// ---------------------------------------------------------------------------
__global__ void k_final(const float* __restrict__ Wd, const float* __restrict__ bd,
                        float* __restrict__ out, int n) {
    int o = threadIdx.x;
    if (o >= 32) return;
    float s = 0.f;
    #pragma unroll
    for (int c = 0; c < 128; c++) s += g_gsum[c] * Wd[c * 32 + o];
    out[o] = s / (float)n + bd[o];
}

// ---------------------------------------------------------------------------
extern "C" void kernel_launch(void* const* d_in, const int* in_sizes, int n_in,
                              void* d_out, int out_size) {
    const float* x     = (const float*)d_in[0];
    const int*   esrc  = (const int*)d_in[1];
    const int*   edst  = (const int*)d_in[2];
    const float* Wp    = (const float*)d_in[3];
    const float* bp    = (const float*)d_in[4];
    const float* Wm    = (const float*)d_in[5];
    const float* bm    = (const float*)d_in[6];
    const float* Wu    = (const float*)d_in[7];
    const float* bu    = (const float*)d_in[8];
    const float* gamma = (const float*)d_in[9];
    const float* beta  = (const float*)d_in[10];
    const float* Wd    = (const float*)d_in[11];
    const float* bd    = (const float*)d_in[12];
    float* out = (float*)d_out;

    int n = in_sizes[0] / 128;
    int e = in_sizes[1];
    int rb = (n + 127) / 128;
    int nb = (n + SCAN_B - 1) / SCAN_B;

    cudaFuncSetAttribute(k_gemm0, cudaFuncAttributeMaxDynamicSharedMemorySize, GSM0);
    cudaFuncSetAttribute(k_gemm1, cudaFuncAttributeMaxDynamicSharedMemorySize, GSM1);

    // Fork resources (host objects; created per call, intentionally not destroyed)
    cudaStream_t side;
    cudaEvent_t evf, evj;
    cudaStreamCreateWithFlags(&side, cudaStreamNonBlocking);
    cudaEventCreateWithFlags(&evf, cudaEventDisableTiming);
    cudaEventCreateWithFlags(&evj, cudaEventDisableTiming);

    // main: zero degrees, then fork
    k_zero_deg<<<(n + 1023) / 1024, 1024>>>(n);
    cudaEventRecord(evf, 0);
    cudaStreamWaitEvent(side, evf, 0);

    // side: CSR build (depends only on edges + deg zero)
    k_hist<<<(e + 255) / 256, 256, 0, side>>>(edst, e);
    k_scan1<<<nb, SCAN_B, 0, side>>>(n);
    k_scan2<<<1, 128, 0, side>>>(nb);
    k_scan3<<<nb, SCAN_B, 0, side>>>(n);
    k_scatter<<<(e + 255) / 256, 256, 0, side>>>(esrc, edst, e);
    cudaEventRecord(evj, side);

    // main (concurrent with side): weights (fp16), then hc | a | b GEMM
    k_prepw<<<192, 256>>>(Wp, bp, Wm, bm, Wu);
    k_gemm0<<<rb, 256, GSM0>>>(x, n);

    // join: gather needs elist (side) + a/b (main)
    cudaStreamWaitEvent(0, evj, 0);
    k_gather<<<(n * 32 + 255) / 256, 256>>>(n);
    // upd-GEMM fused with relu+LN+graph-pool
    k_gemm1<<<rb, 256, GSM1>>>(Wu + 16384, bu, gamma, beta, n);
    k_final<<<1, 32>>>(Wd, bd, out, n);
}

// round 16
// speedup vs baseline: 2.9142x; 1.0052x over previous
#include <cuda_runtime.h>
#include <cuda_fp16.h>
#include <mma.h>
#include <cstdint>

using namespace nvcuda;

// Problem constants: N=50000, E=640000, D=H=128, OUT=32
#define MAXN 50000
#define MAXE 640000
#define SCAN_B 1024
#define MAXBLK 64

// Scratch (device globals — no allocation allowed)
__device__ half  g_W3h[3 * 16384];    // fp16 blocked: [Wp+Wp@WuA][Wp@WmA][Wp@WmB]
__device__ half  g_Wuh[16384];        // fp16 WuB (Wu rows 128..255)
__device__ float g_b3[384];           // [bp+bp@WuA | bp@WmA | bp@WmB+bm]
__device__ half2 g_hc[MAXN * 64];     // hc = h0 + c              fp16
__device__ half2 g_a[MAXN * 64];      // a = h0@WmA               fp16
__device__ half2 g_b[MAXN * 64];      // b = h0@WmB + bm          fp16
__device__ half2 g_pool[MAXN * 64];   // pooled mean              fp16
__device__ float g_gsum[128];         // graph-level sum of normalized hn
__device__ int   g_deg[MAXN];         // per-dst degree
__device__ int   g_off[MAXN];         // CSR offsets
__device__ int   g_cur[MAXN];         // scatter cursors
__device__ int   g_elist[MAXE];       // src ids grouped by dst
__device__ int   g_bsum[MAXBLK];      // per-block scan totals

#define LDH 136
#define LDC 132
#define SM_A_BYTES (128 * LDH * 2)          // 34816
#define GSM0 (SM_A_BYTES + 128 * LDC * 4)   // 102400
#define SACC_OFF (2 * SM_A_BYTES)           // 69632
#define GSM1 (SACC_OFF + 4096)              // 73728

// ---------------------------------------------------------------------------
__global__ void k_zero_deg(int n) {
    int i = blockIdx.x * blockDim.x + threadIdx.x;
    if (i < n) g_deg[i] = 0;
}

// ---------------------------------------------------------------------------
// Combined weight build -> fp16 blocked layout; also convert WuB to fp16.
// blk 0: Wp + Wp@WuA, 1: Wp@WmA, 2: Wp@WmB, 3: raw WuB convert.
// ---------------------------------------------------------------------------
__global__ void k_prepw(const float* __restrict__ Wp, const float* __restrict__ bp,
                        const float* __restrict__ Wm, const float* __restrict__ bm,
                        const float* __restrict__ Wu) {
    int idx = blockIdx.x * blockDim.x + threadIdx.x;
    if (idx < 4 * 16384) {
        int blk = idx >> 14;
        int rem = idx & 16383;
        if (blk == 3) {
            g_Wuh[rem] = __float2half(Wu[16384 + rem]);
        } else {
            int i = rem >> 7, jj = rem & 127;
            const float* M = (blk == 0) ? Wu : ((blk == 1) ? Wm : Wm + 16384);
            float s = (blk == 0) ? Wp[i * 128 + jj] : 0.f;
            for (int k = 0; k < 128; k++) s += Wp[i * 128 + k] * M[k * 128 + jj];
            g_W3h[blk * 16384 + i * 128 + jj] = __float2half(s);
        }
    }
    if (idx < 384) {
        int blk = idx >> 7, jj = idx & 127;
        const float* M = (blk == 0) ? Wu : ((blk == 1) ? Wm : Wm + 16384);
        float s = (blk == 0) ? bp[jj] : ((blk == 2) ? bm[jj] : 0.f);
        for (int k = 0; k < 128; k++) s += bp[k] * M[k * 128 + jj];
        g_b3[idx] = s;
    }
}

// ---------------------------------------------------------------------------
// gemm0: one CTA per 128-row block; A filled once (fp32->fp16), loop over the
// 3 fp16 weight column-blocks: fill B (raw copy) -> MMA -> epilogue (all fp16).
// Outputs: cb 0 -> g_hc, 1 -> g_a, 2 -> g_b.
// ---------------------------------------------------------------------------
__global__ void __launch_bounds__(256, 2) k_gemm0(const float* __restrict__ X, int n) {
    extern __shared__ __align__(16) char smw[];
    half*  As = (half*)smw;
    half*  Bs = (half*)(smw + SM_A_BYTES);
    float* Cs = (float*)(smw + SM_A_BYTES);     // overlaps Bs (phased by syncs)

    const int tid = threadIdx.x;
    const int wid = tid >> 5;
    const int rowBase = blockIdx.x * 128;

    // ---- Fill A once ----
    const float4* X4 = (const float4*)X;
    #pragma unroll
    for (int it = 0; it < 16; it++) {
        int i = tid + it * 256;
        int m = i >> 5, c4 = i & 31;
        int row = rowBase + m;
        float4 v = make_float4(0.f, 0.f, 0.f, 0.f);
        if (row < n) v = X4[(size_t)row * 32 + c4];
        half2* da = (half2*)&As[m * LDH + c4 * 4];
        da[0] = __floats2half2_rn(v.x, v.y);
        da[1] = __floats2half2_rn(v.z, v.w);
    }

    const int wrow = (wid & 3) * 32;
    const int wcol = (wid >> 2) * 64;
    const float4* b4 = (const float4*)g_b3;

    for (int cb = 0; cb < 3; cb++) {
        __syncthreads();   // A ready (cb=0) / previous epilogue done reading Cs
        // ---- Fill B: raw fp16 copy, 32KB ----
        const uint4* Wsrc = (const uint4*)(g_W3h + cb * 16384);
        #pragma unroll
        for (int it = 0; it < 8; it++) {
            int i = tid + it * 256;
            int r = i >> 4, c16 = i & 15;
            *(uint4*)&Bs[r * LDH + c16 * 8] = Wsrc[r * 16 + c16];
        }
        __syncthreads();

        // ---- MMA ----
        wmma::fragment<wmma::accumulator, 16, 16, 16, float> acc[2][4];
        #pragma unroll
        for (int r = 0; r < 2; r++)
            #pragma unroll
            for (int c = 0; c < 4; c++) wmma::fill_fragment(acc[r][c], 0.0f);
        #pragma unroll
        for (int kk = 0; kk < 8; kk++) {
            wmma::fragment<wmma::matrix_a, 16, 16, 16, half, wmma::row_major> af[2];
            wmma::fragment<wmma::matrix_b, 16, 16, 16, half, wmma::row_major> bf[4];
            #pragma unroll
            for (int r = 0; r < 2; r++)
                wmma::load_matrix_sync(af[r], &As[(wrow + r * 16) * LDH + kk * 16], LDH);
            #pragma unroll
            for (int c = 0; c < 4; c++)
                wmma::load_matrix_sync(bf[c], &Bs[(kk * 16) * LDH + wcol + c * 16], LDH);
            #pragma unroll
            for (int r = 0; r < 2; r++)
                #pragma unroll
                for (int c = 0; c < 4; c++)
                    wmma::mma_sync(acc[r][c], af[r], bf[c], acc[r][c]);
        }
        __syncthreads();   // all warps done reading Bs before Cs overwrite

        #pragma unroll
        for (int r = 0; r < 2; r++)
            #pragma unroll
            for (int c = 0; c < 4; c++)
                wmma::store_matrix_sync(&Cs[(wrow + r * 16) * LDC + wcol + c * 16],
                                        acc[r][c], LDC, wmma::mem_row_major);
        __syncthreads();

        // ---- Epilogue for this column block (all fp16 outputs) ----
        half2* dstp = (cb == 0) ? g_hc : ((cb == 1) ? g_a : g_b);
        #pragma unroll
        for (int it = 0; it < 16; it++) {
            int i = tid + it * 256;
            int m = i >> 5, c4 = i & 31;
            int row = rowBase + m;
            if (row >= n) continue;
            float4 v = *(float4*)&Cs[m * LDC + c4 * 4];
            float4 bv = b4[cb * 32 + c4];
            v.x += bv.x; v.y += bv.y; v.z += bv.z; v.w += bv.w;
            half2 h0 = __floats2half2_rn(v.x, v.y);
            half2 h1 = __floats2half2_rn(v.z, v.w);
            dstp[(size_t)row * 64 + c4 * 2]     = h0;
            dstp[(size_t)row * 64 + c4 * 2 + 1] = h1;
        }
    }
}

// ---------------------------------------------------------------------------
// gemm1: fused upd-GEMM (pool fp16 @ WuB fp16) + relu + LayerNorm + graph-pool.
// ---------------------------------------------------------------------------
__global__ void __launch_bounds__(256, 2) k_gemm1(const float* __restrict__ biasExt,
                                                  const float* __restrict__ gamma,
                                                  const float* __restrict__ beta,
                                                  int n) {
    extern __shared__ __align__(16) char smw[];
    half*  As = (half*)smw;
    half*  Bs = (half*)(smw + SM_A_BYTES);
    float* Cs = (float*)smw;                    // overlaps A+B (after sync)
    float* sacc = (float*)(smw + SACC_OFF);     // [8][128] LN partials

    const int rowBase = blockIdx.x * 128;
    const int tid = threadIdx.x;
    const int wid = tid >> 5;
    const int lane = tid & 31;

    // ---- Fill A (raw fp16 pool copy) ----
    const uint2* P2 = (const uint2*)g_pool;
    #pragma unroll
    for (int it = 0; it < 16; it++) {
        int i = tid + it * 256;
        int m = i >> 5, c4 = i & 31;
        int row = rowBase + m;
        uint2 u = make_uint2(0u, 0u);
        if (row < n) u = __ldg(P2 + (size_t)row * 32 + c4);
        *(uint2*)&As[m * LDH + c4 * 4] = u;
    }
    // ---- Fill B (raw fp16 WuB copy) ----
    const uint4* Wsrc = (const uint4*)g_Wuh;
    #pragma unroll
    for (int it = 0; it < 8; it++) {
        int i = tid + it * 256;
        int r = i >> 4, c16 = i & 15;
        *(uint4*)&Bs[r * LDH + c16 * 8] = Wsrc[r * 16 + c16];
    }
    __syncthreads();

    const int wrow = (wid & 3) * 32;
    const int wcol = (wid >> 2) * 64;

    wmma::fragment<wmma::accumulator, 16, 16, 16, float> acc[2][4];
    #pragma unroll
    for (int r = 0; r < 2; r++)
        #pragma unroll
        for (int c = 0; c < 4; c++) wmma::fill_fragment(acc[r][c], 0.0f);

    #pragma unroll
    for (int kk = 0; kk < 8; kk++) {
        wmma::fragment<wmma::matrix_a, 16, 16, 16, half, wmma::row_major> af[2];
        wmma::fragment<wmma::matrix_b, 16, 16, 16, half, wmma::row_major> bf[4];
        #pragma unroll
        for (int r = 0; r < 2; r++)
            wmma::load_matrix_sync(af[r], &As[(wrow + r * 16) * LDH + kk * 16], LDH);
        #pragma unroll
        for (int c = 0; c < 4; c++)
            wmma::load_matrix_sync(bf[c], &Bs[(kk * 16) * LDH + wcol + c * 16], LDH);
        #pragma unroll
        for (int r = 0; r < 2; r++)
            #pragma unroll
            for (int c = 0; c < 4; c++)
                wmma::mma_sync(acc[r][c], af[r], bf[c], acc[r][c]);
    }

    __syncthreads();
    #pragma unroll
    for (int r = 0; r < 2; r++)
        #pragma unroll
        for (int c = 0; c < 4; c++)
            wmma::store_matrix_sync(&Cs[(wrow + r * 16) * LDC + wcol + c * 16],
                                    acc[r][c], LDC, wmma::mem_row_major);
    __syncthreads();

    // ---- Fused: relu(hc+upd+bu) + LayerNorm + graph-pool partials ----
    const float4* b4 = (const float4*)biasExt;
    float4 ga = ((const float4*)gamma)[lane];
    float4 be = ((const float4*)beta)[lane];
    float ax = 0.f, ay = 0.f, az = 0.f, aw = 0.f;
    float4 bv = b4[lane];   // bu
    const uint2* HC2 = (const uint2*)g_hc;

    #pragma unroll
    for (int it = 0; it < 16; it++) {
        int m = wid + it * 8;             // one warp <-> one row
        int row = rowBase + m;
        if (row >= n) continue;
        float4 u = *(float4*)&Cs[m * LDC + lane * 4];
        uint2 hcu = __ldg(HC2 + (size_t)row * 32 + lane);
        float2 hc01 = __half22float2(*(half2*)&hcu.x);
        float2 hc23 = __half22float2(*(half2*)&hcu.y);
        float vx = fmaxf(hc01.x + u.x + bv.x, 0.f);
        float vy = fmaxf(hc01.y + u.y + bv.y, 0.f);
        float vz = fmaxf(hc23.x + u.z + bv.z, 0.f);
        float vw = fmaxf(hc23.y + u.w + bv.w, 0.f);

        float s1 = vx + vy + vz + vw;
        float s2 = vx * vx + vy * vy + vz * vz + vw * vw;
        #pragma unroll
        for (int o = 16; o > 0; o >>= 1) {
            s1 += __shfl_xor_sync(0xFFFFFFFFu, s1, o);
            s2 += __shfl_xor_sync(0xFFFFFFFFu, s2, o);
        }
        float mu  = s1 * (1.f / 128.f);
        float var = s2 * (1.f / 128.f) - mu * mu;
        float is  = rsqrtf(var + 1e-6f);
        ax += (vx - mu) * is * ga.x + be.x;
        ay += (vy - mu) * is * ga.y + be.y;
        az += (vz - mu) * is * ga.z + be.z;
        aw += (vw - mu) * is * ga.w + be.w;
    }

    sacc[wid * 128 + lane * 4 + 0] = ax;
    sacc[wid * 128 + lane * 4 + 1] = ay;
    sacc[wid * 128 + lane * 4 + 2] = az;
    sacc[wid * 128 + lane * 4 + 3] = aw;
    __syncthreads();
    if (tid < 128) {
        float s = 0.f;
        #pragma unroll
        for (int ww = 0; ww < 8; ww++) s += sacc[ww * 128 + tid];
        atomicAdd(&g_gsum[tid], s);
    }
}

// ---------------------------------------------------------------------------
// CSR build: histogram -> 3-phase multi-block scan -> scatter
// ---------------------------------------------------------------------------
__global__ void k_hist(const int* __restrict__ dst, int e) {
    int i = blockIdx.x * blockDim.x + threadIdx.x;
    if (i < e) atomicAdd(&g_deg[dst[i]], 1);
}

__global__ void __launch_bounds__(SCAN_B) k_scan1(int n) {
    __shared__ int wsum[32];
    int tid = threadIdx.x;
    int lane = tid & 31, wd = tid >> 5;
    int i = blockIdx.x * SCAN_B + tid;
    int d = (i < n) ? g_deg[i] : 0;
    int v = d;
    #pragma unroll
    for (int o = 1; o < 32; o <<= 1) {
        int t = __shfl_up_sync(0xFFFFFFFFu, v, o);
        if (lane >= o) v += t;
    }
    if (lane == 31) wsum[wd] = v;
    __syncthreads();
    if (wd == 0) {
        int w = wsum[lane];
        #pragma unroll
        for (int o = 1; o < 32; o <<= 1) {
            int t = __shfl_up_sync(0xFFFFFFFFu, w, o);
            if (lane >= o) w += t;
        }
        wsum[lane] = w;
    }
    __syncthreads();
    int excl = v - d + (wd ? wsum[wd - 1] : 0);
    if (i < n) g_off[i] = excl;
    if (tid == SCAN_B - 1) g_bsum[blockIdx.x] = excl + d;
}

__global__ void k_scan2(int nb) {
    int tid = threadIdx.x;
    if (tid < 64) {
        int v = (tid < nb) ? g_bsum[tid] : 0;
        int lane = tid & 31, wd = tid >> 5;
        __shared__ int lo_total;
        #pragma unroll
        for (int o = 1; o < 32; o <<= 1) {
            int t = __shfl_up_sync(0xFFFFFFFFu, v, o);
            if (lane >= o) v += t;
        }
        if (wd == 0 && lane == 31) lo_total = v;
        __syncthreads();
        if (wd == 1) v += lo_total;
        if (tid < nb) g_bsum[tid] = v;
    }
    if (tid < 128) g_gsum[tid] = 0.f;
}

__global__ void __launch_bounds__(SCAN_B) k_scan3(int n) {
    int b = blockIdx.x;
    int i = b * SCAN_B + threadIdx.x;
    if (i >= n) return;
    int add = (b > 0) ? g_bsum[b - 1] : 0;
    int o = g_off[i] + add;
    g_off[i] = o;
    g_cur[i] = o;
}

__global__ void k_scatter(const int* __restrict__ src, const int* __restrict__ dst, int e) {
    int i = blockIdx.x * blockDim.x + threadIdx.x;
    if (i < e) {
        int pos = atomicAdd(&g_cur[dst[i]], 1);
        g_elist[pos] = src[i];
    }
}

// ---------------------------------------------------------------------------
// Gather: warp per node d. pooled[d] = mean over edges of relu(a[src]+b[d]).
// uint2 (8B) loads; 2-deep software pipeline.
// ---------------------------------------------------------------------------
__global__ void __launch_bounds__(256) k_gather(int n) {
    int w = (blockIdx.x * blockDim.x + threadIdx.x) >> 5;
    if (w >= n) return;
    int lane = threadIdx.x & 31;
    int off = g_off[w], deg = g_deg[w];

    uint2 ub = __ldg(((const uint2*)g_b) + (size_t)w * 32 + lane);
    float2 vb01 = __half22float2(*(half2*)&ub.x);
    float2 vb23 = __half22float2(*(half2*)&ub.y);
    float ax = 0.f, ay = 0.f, az = 0.f, aw = 0.f;

    const uint2* A2 = (const uint2*)g_a;
    if (deg > 0) {
        int s = g_elist[off];
        uint2 pa = __ldg(A2 + (size_t)s * 32 + lane);
        for (int j = 0; j < deg; j++) {
            int s2 = (j + 1 < deg) ? g_elist[off + j + 1] : 0;
            uint2 na = __ldg(A2 + (size_t)s2 * 32 + lane);
            float2 a01 = __half22float2(*(half2*)&pa.x);
            float2 a23 = __half22float2(*(half2*)&pa.y);
            ax += fmaxf(a01.x + vb01.x, 0.f);
            ay += fmaxf(a01.y + vb01.y, 0.f);
            az += fmaxf(a23.x + vb23.x, 0.f);
            aw += fmaxf(a23.y + vb23.y, 0.f);
            pa = na;
        }
    }
    float rc = 1.0f / (float)max(deg, 1);
    half2 o01 = __floats2half2_rn(ax * rc, ay * rc);
    half2 o23 = __floats2half2_rn(az * rc, aw * rc);
    g_pool[(size_t)w * 64 + lane * 2]     = o01;
    g_pool[(size_t)w * 64 + lane * 2 + 1] = o23;
}

// ---------------------------------------------------------------------------
__global__ void k_final(const float* __restrict__ Wd, const float* __restrict__ bd,
                        float* __restrict__ out, int n) {
    int o = threadIdx.x;
    if (o >= 32) return;
    float s = 0.f;
    #pragma unroll
    for (int c = 0; c < 128; c++) s += g_gsum[c] * Wd[c * 32 + o];
    out[o] = s / (float)n + bd[o];
}

// ---------------------------------------------------------------------------
extern "C" void kernel_launch(void* const* d_in, const int* in_sizes, int n_in,
                              void* d_out, int out_size) {
    const float* x     = (const float*)d_in[0];
    const int*   esrc  = (const int*)d_in[1];
    const int*   edst  = (const int*)d_in[2];
    const float* Wp    = (const float*)d_in[3];
    const float* bp    = (const float*)d_in[4];
    const float* Wm    = (const float*)d_in[5];
    const float* bm    = (const float*)d_in[6];
    const float* Wu    = (const float*)d_in[7];
    const float* bu    = (const float*)d_in[8];
    const float* gamma = (const float*)d_in[9];
    const float* beta  = (const float*)d_in[10];
    const float* Wd    = (const float*)d_in[11];
    const float* bd    = (const float*)d_in[12];
    float* out = (float*)d_out;

    int n = in_sizes[0] / 128;
    int e = in_sizes[1];
    int rb = (n + 127) / 128;
    int nb = (n + SCAN_B - 1) / SCAN_B;

    cudaFuncSetAttribute(k_gemm0, cudaFuncAttributeMaxDynamicSharedMemorySize, GSM0);
    cudaFuncSetAttribute(k_gemm1, cudaFuncAttributeMaxDynamicSharedMemorySize, GSM1);

    // Fork resources (host objects; created per call, intentionally not destroyed)
    cudaStream_t side;
    cudaEvent_t evf, evj;
    cudaStreamCreateWithFlags(&side, cudaStreamNonBlocking);
    cudaEventCreateWithFlags(&evf, cudaEventDisableTiming);
    cudaEventCreateWithFlags(&evj, cudaEventDisableTiming);

    // fork immediately: side owns the whole CSR chain
    cudaEventRecord(evf, 0);
    cudaStreamWaitEvent(side, evf, 0);

    // side: CSR build (depends only on edges)
    k_zero_deg<<<(n + 1023) / 1024, 1024, 0, side>>>(n);
    k_hist<<<(e + 255) / 256, 256, 0, side>>>(edst, e);
    k_scan1<<<nb, SCAN_B, 0, side>>>(n);
    k_scan2<<<1, 128, 0, side>>>(nb);
    k_scan3<<<nb, SCAN_B, 0, side>>>(n);
    k_scatter<<<(e + 255) / 256, 256, 0, side>>>(esrc, edst, e);
    cudaEventRecord(evj, side);

    // main (concurrent with side): weights (fp16), then hc | a | b GEMM
    k_prepw<<<256, 256>>>(Wp, bp, Wm, bm, Wu);
    k_gemm0<<<rb, 256, GSM0>>>(x, n);

    // join: gather needs elist (side) + a/b (main)
    cudaStreamWaitEvent(0, evj, 0);
    k_gather<<<(n * 32 + 255) / 256, 256>>>(n);
    // upd-GEMM fused with relu+LN+graph-pool
    k_gemm1<<<rb, 256, GSM1>>>(bu, gamma, beta, n);
    k_final<<<1, 32>>>(Wd, bd, out, n);
}